// round 14
// baseline (speedup 1.0000x reference)
#include <cuda_runtime.h>
#include <cuda_fp16.h>
#include <math.h>
#include <stdint.h>

// Problem constants
#define BB   2
#define LL   4096
#define DIMD 1024
#define NH   16
#define HD   64
#define MROWS (BB * LL)          // 8192
#define KDIM 1024
#define CHUNK  64
#define NCHUNK (LL / CHUNK)      // 64
#define NCID   (BB * NH * NCHUNK) // 2048
#define NPJ  7168                // fused projection width: q|k|v|i|f|o|gate
#define PGRID 296                // persistent GEMM grid (2 CTAs/SM x 148)

// ---------------------------------------------------------------------------
// Scratch
// ---------------------------------------------------------------------------
__device__ float g_pj[(size_t)MROWS * NPJ];
__device__ __half g_xh  [(size_t)MROWS * 1024];
__device__ __half g_hh  [(size_t)MROWS * 1024];
__device__ __half g_wiT [(size_t)1024 * 1024];
__device__ __half g_w6h [(size_t)6 * 1024 * 1024];
__device__ __half g_w6l [(size_t)6 * 1024 * 1024];
__device__ __half g_wff [(size_t)NPJ * 1024];
__device__ __half g_wof [(size_t)1024 * 1024];
__device__ float g_dC  [(size_t)NCID * 4096];
__device__ float g_dN  [(size_t)NCID * 64];
__device__ float g_G   [(size_t)NCID * 64];
__device__ float g_Cst [(size_t)NCID * 4096];
__device__ float g_Nst [(size_t)NCID * 64];
__device__ float g_numI[(size_t)NCID * 4096];
__device__ float g_qd  [(size_t)NCID * 4096];
__device__ float g_denI[(size_t)NCID * 64];

// ---------------------------------------------------------------------------
// helpers
// ---------------------------------------------------------------------------
__device__ __forceinline__ uint32_t packh(float x, float y) {
    __half hx = __float2half_rn(x);
    __half hy = __float2half_rn(y);
    return (uint32_t)__half_as_ushort(hx) | ((uint32_t)__half_as_ushort(hy) << 16);
}
__device__ __forceinline__ uint32_t packhl(float x, float y) {
    __half hx = __float2half_rn(x);
    __half hy = __float2half_rn(y);
    return packh(x - __half2float(hx), y - __half2float(hy));
}
__device__ __forceinline__ void cp16(uint32_t s, const void* g)
{
    asm volatile("cp.async.ca.shared.global [%0], [%1], 16;\n" :: "r"(s), "l"(g));
}

#define LDSM_X4(r0, r1, r2, r3, addr) \
    asm volatile("ldmatrix.sync.aligned.m8n8.x4.shared.b16 {%0,%1,%2,%3}, [%4];" \
                 : "=r"(r0), "=r"(r1), "=r"(r2), "=r"(r3) : "r"(addr))

#define MMA_F16(d, a, b0, b1) \
    asm volatile("mma.sync.aligned.m16n8k16.row.col.f32.f16.f16.f32 " \
                 "{%0,%1,%2,%3}, {%4,%5,%6,%7}, {%8,%9}, {%0,%1,%2,%3};" \
                 : "+f"((d)[0]), "+f"((d)[1]), "+f"((d)[2]), "+f"((d)[3]) \
                 : "r"((a)[0]), "r"((a)[1]), "r"((a)[2]), "r"((a)[3]), \
                   "r"(b0), "r"(b1))

// ---------------------------------------------------------------------------
// Pass 0: fused conversion mega-kernel (grid-stride over 4 regions)
//   r0: x (fp32) -> xh           [2,097,152 float4 groups]
//   r1: w_in rows 1024..2047 -> wff rows 6144..7167   [262,144]
//   r2: w_q..w_o -> (w6h, w6l) split                  [1,572,864]
//   r3: w_out -> wof                                  [262,144]
// ---------------------------------------------------------------------------
#define R0N 2097152
#define R1N 262144
#define R2N 1572864
#define R3N 262144
#define RTOT (R0N + R1N + R2N + R3N)

__global__ void cvt_all(const float4* __restrict__ x,
                        const float4* __restrict__ wgate,
                        const float4* __restrict__ w0, const float4* __restrict__ w1,
                        const float4* __restrict__ w2, const float4* __restrict__ w3,
                        const float4* __restrict__ w4, const float4* __restrict__ w5,
                        const float4* __restrict__ wout,
                        uint2* __restrict__ xh, uint2* __restrict__ wffgate,
                        uint2* __restrict__ w6h, uint2* __restrict__ w6l,
                        uint2* __restrict__ wof)
{
    for (int idx = blockIdx.x * 256 + threadIdx.x; idx < RTOT; idx += gridDim.x * 256) {
        if (idx < R0N) {
            float4 v = x[idx];
            xh[idx] = make_uint2(packh(v.x, v.y), packh(v.z, v.w));
        } else if (idx < R0N + R1N) {
            const int i = idx - R0N;
            float4 v = wgate[i];
            wffgate[i] = make_uint2(packh(v.x, v.y), packh(v.z, v.w));
        } else if (idx < R0N + R1N + R2N) {
            const int l = idx - R0N - R1N;
            const int which = l >> 18;           // /262144
            const int i = l & 262143;
            const float4* s;
            switch (which) {
                case 0: s = w0; break; case 1: s = w1; break; case 2: s = w2; break;
                case 3: s = w3; break; case 4: s = w4; break; default: s = w5; break;
            }
            float4 v = s[i];
            w6h[l] = make_uint2(packh(v.x, v.y),  packh(v.z, v.w));
            w6l[l] = make_uint2(packhl(v.x, v.y), packhl(v.z, v.w));
        } else {
            const int i = idx - R0N - R1N - R2N;
            float4 v = wout[i];
            wof[i] = make_uint2(packh(v.x, v.y), packh(v.z, v.w));
        }
    }
}

__global__ void transpose_wi(const float* __restrict__ w, __half* __restrict__ wt)
{
    __shared__ float tile[32][33];
    const int bx = blockIdx.x * 32, by = blockIdx.y * 32;
    const int tx = threadIdx.x & 31, ty = threadIdx.x >> 5;
#pragma unroll
    for (int dy = 0; dy < 32; dy += 8)
        tile[ty + dy][tx] = w[(size_t)(by + ty + dy) * 1024 + bx + tx];
    __syncthreads();
#pragma unroll
    for (int dy = 0; dy < 32; dy += 8)
        wt[(size_t)(bx + ty + dy) * 1024 + by + tx] = __float2half_rn(tile[tx][ty + dy]);
}

// ---------------------------------------------------------------------------
// Persistent cp.async pipelined fp16 GEMM.
// C[tile] over MT x NT tiles of 128x128; grid = PGRID CTAs, each loops tiles
// blockIdx.x + i*PGRID with a k-step pipeline linearized ACROSS tiles
// (steps 29..31 of tile t prefetch stages 0..2 of tile t+1 -> no drain).
// TERMS: 2 = split A (hi+lo); 1 = single fp16 A.
// MODE:  0 = fp16 output Chh; 1 = projections (per-1024-col-seg epilogue);
//        2 = fp32 C.
// ---------------------------------------------------------------------------
#define STAGES 4
#define SECB   8192
#define STAGEB (3 * SECB)
#define GEMM_SMEM (STAGES * STAGEB)

template <int MODE, int TERMS>
__global__ void __launch_bounds__(128, 2)
gemm_f16(const __half* __restrict__ Ah, const __half* __restrict__ Al, int lda,
         const __half* __restrict__ B,
         const float* __restrict__ q0, const float* __restrict__ q1,
         const float* __restrict__ q2, const float* __restrict__ q3,
         const float* __restrict__ q4,
         float* __restrict__ C, int ldc,
         __half* __restrict__ Chh,
         int MT, int NT)
{
    extern __shared__ __align__(128) char smem[];
    const uint32_t sbase = (uint32_t)__cvta_generic_to_shared(smem);

    const int tid  = threadIdx.x;
    const int w    = tid >> 5;
    const int lane = tid & 31;
    const int wm   = w & 1;
    const int wn   = w >> 1;

    const int tiles = MT * NT;
    const int nt    = (tiles - (int)blockIdx.x + PGRID - 1) / PGRID;
    const int Gtot  = nt * 32;

    // loader for global k-step g (within this CTA's linearized tile sequence)
    auto load_g = [&](int g) {
        const int ti   = g >> 5;
        const int s    = g & 31;
        const int tile = (int)blockIdx.x + ti * PGRID;
        const int m0   = (tile / NT) * 128;
        const int n0   = (tile % NT) * 128;
        const __half* Ahp = Ah + (size_t)m0 * lda;
        const __half* Alp = (TERMS == 2) ? (Al + (size_t)m0 * lda) : nullptr;
        const __half* Bp  = B  + (size_t)n0 * KDIM;
        const int k0 = s * 32;
        const uint32_t db = sbase + (uint32_t)((g & (STAGES - 1)) * STAGEB);
        const int NCH = (TERMS == 2) ? 12 : 8;
#pragma unroll
        for (int i = 0; i < NCH; i++) {
            const int ci  = tid + i * 128;
            const int s2  = ci >> 9;
            const int r   = (ci >> 2) & 127;
            const int kq  = ci & 3;
            const __half* gp;
            uint32_t secoff;
            if (TERMS == 2) {
                if      (s2 == 0) { gp = Ahp + (size_t)r * lda; secoff = 0; }
                else if (s2 == 1) { gp = Alp + (size_t)r * lda; secoff = SECB; }
                else              { gp = Bp  + (size_t)r * KDIM; secoff = 2 * SECB; }
            } else {
                if (s2 == 0) { gp = Ahp + (size_t)r * lda; secoff = 0; }
                else         { gp = Bp  + (size_t)r * KDIM; secoff = 2 * SECB; }
            }
            gp += k0 + kq * 8;
            const uint32_t d = db + secoff + (uint32_t)(r * 64 + ((kq * 16) ^ ((r * 8) & 0x30)));
            cp16(d, gp);
        }
    };

    // ldmatrix per-lane addressing (SW64)
    const int a_r  = (lane & 7) + ((lane >> 3) & 1) * 8;
    const int ak2  = ((lane >> 4) & 1) * 16;
    const uint32_t axr = (uint32_t)((a_r << 3) & 0x30);
    const int g_   = lane >> 3;
    const int b_r  = ((g_ >> 1) * 8) + (lane & 7);
    const int bk2  = (g_ & 1) * 16;
    const uint32_t bxr = (uint32_t)((b_r << 3) & 0x30);

    uint32_t aoff[4], boff[4];
#pragma unroll
    for (int mi = 0; mi < 4; mi++) aoff[mi] = (uint32_t)((wm * 64 + mi * 16 + a_r) * 64);
#pragma unroll
    for (int gi = 0; gi < 4; gi++) boff[gi] = (uint32_t)(2 * SECB + (wn * 64 + gi * 16 + b_r) * 64);

    const int qr = lane >> 2;
    const int qc = (lane & 3) * 2;

    // pipeline prologue
    load_g(0); asm volatile("cp.async.commit_group;\n");
    load_g(1); asm volatile("cp.async.commit_group;\n");
    load_g(2); asm volatile("cp.async.commit_group;\n");

    for (int ti = 0; ti < nt; ti++) {
        const int tile = (int)blockIdx.x + ti * PGRID;
        const int mtl  = tile / NT;
        const int ntl  = tile % NT;
        const int m0   = mtl * 128;
        const int n0   = ntl * 128;

        float acc[4][8][4] = {};

        for (int s = 0; s < 32; s++) {
            const int g = ti * 32 + s;
            asm volatile("cp.async.wait_group 2;\n" ::: "memory");
            __syncthreads();
            if (g + 3 < Gtot) load_g(g + 3);
            asm volatile("cp.async.commit_group;\n");

            const uint32_t bb = sbase + (uint32_t)((g & (STAGES - 1)) * STAGEB);
#pragma unroll
            for (int kb = 0; kb < 2; kb++) {
                const uint32_t kx = (uint32_t)(kb * 32);
                uint32_t Bf[4][4];
#pragma unroll
                for (int gi = 0; gi < 4; gi++) {
                    const uint32_t ba = bb + boff[gi] + ((kx + bk2) ^ bxr);
                    LDSM_X4(Bf[gi][0], Bf[gi][1], Bf[gi][2], Bf[gi][3], ba);
                }
                {
                    uint32_t Af[4][4];
#pragma unroll
                    for (int mi = 0; mi < 4; mi++) {
                        const uint32_t aa = bb + aoff[mi] + ((kx + ak2) ^ axr);
                        LDSM_X4(Af[mi][0], Af[mi][1], Af[mi][2], Af[mi][3], aa);
                    }
#pragma unroll
                    for (int gi = 0; gi < 4; gi++)
#pragma unroll
                        for (int mi = 0; mi < 4; mi++)
#pragma unroll
                            for (int hf = 0; hf < 2; hf++)
                                MMA_F16(acc[mi][gi * 2 + hf], Af[mi], Bf[gi][2 * hf], Bf[gi][2 * hf + 1]);
                }
                if (TERMS == 2) {
                    uint32_t Af[4][4];
#pragma unroll
                    for (int mi = 0; mi < 4; mi++) {
                        const uint32_t aa = bb + aoff[mi] + ((kx + ak2) ^ axr) + SECB;
                        LDSM_X4(Af[mi][0], Af[mi][1], Af[mi][2], Af[mi][3], aa);
                    }
#pragma unroll
                    for (int gi = 0; gi < 4; gi++)
#pragma unroll
                        for (int mi = 0; mi < 4; mi++)
#pragma unroll
                            for (int hf = 0; hf < 2; hf++)
                                MMA_F16(acc[mi][gi * 2 + hf], Af[mi], Bf[gi][2 * hf], Bf[gi][2 * hf + 1]);
                }
            }
        }

        // ---- epilogue for this tile ----
        const int seg = ntl >> 3;

        if (MODE == 1 && seg < 2) {
            const float* wn_ = (seg == 0) ? q0 : q1;
#pragma unroll
            for (int mi = 0; mi < 4; mi++)
#pragma unroll
                for (int rh = 0; rh < 2; rh++) {
                    float ss = 0.0f;
#pragma unroll
                    for (int tti = 0; tti < 8; tti++) {
                        float a = acc[mi][tti][2 * rh], b2 = acc[mi][tti][2 * rh + 1];
                        ss += a * a + b2 * b2;
                    }
                    ss += __shfl_xor_sync(0xffffffffu, ss, 1);
                    ss += __shfl_xor_sync(0xffffffffu, ss, 2);
                    const float sc = rsqrtf(ss * (1.0f / 64.0f) + 1e-6f);
#pragma unroll
                    for (int tti = 0; tti < 8; tti++) {
                        acc[mi][tti][2 * rh]     *= sc * wn_[tti * 8 + qc];
                        acc[mi][tti][2 * rh + 1] *= sc * wn_[tti * 8 + qc + 1];
                    }
                }
        }

#pragma unroll
        for (int mi = 0; mi < 4; mi++) {
#pragma unroll
            for (int tti = 0; tti < 8; tti++) {
                const int col = n0 + wn * 64 + tti * 8 + qc;
                float b0 = 0.f, b1 = 0.f;
                if (MODE == 1 && seg >= 3 && seg <= 5) {
                    const float* bp = (seg == 3) ? q2 : (seg == 4) ? q3 : q4;
                    const int cs = col & 1023;
                    b0 = bp[cs]; b1 = bp[cs + 1];
                }
#pragma unroll
                for (int rh = 0; rh < 2; rh++) {
                    const int row = m0 + wm * 64 + mi * 16 + rh * 8 + qr;
                    float x0 = acc[mi][tti][2 * rh + 0];
                    float x1 = acc[mi][tti][2 * rh + 1];
                    if (MODE == 1) {
                        if (seg == 3)                  { x0 = expf(x0 + b0); x1 = expf(x1 + b1); }
                        else if (seg == 4 || seg == 5) { x0 = 1.0f / (1.0f + expf(-(x0 + b0)));
                                                         x1 = 1.0f / (1.0f + expf(-(x1 + b1))); }
                    }
                    if (MODE == 0) {
                        *(uint32_t*)&Chh[(size_t)row * ldc + col] = packh(x0, x1);
                    } else {
                        *(float2*)&C[(size_t)row * ldc + col] = make_float2(x0, x1);
                    }
                }
            }
        }
    }
}

// ---------------------------------------------------------------------------
// Scan pass A (unchanged from R13)
// ---------------------------------------------------------------------------
__global__ void __launch_bounds__(128, 4)
chunk_fwdA(const float* __restrict__ pj,
           float* __restrict__ dC, float* __restrict__ dN, float* __restrict__ G,
           float* __restrict__ numI, float* __restrict__ qd, float* __restrict__ denI)
{
    __shared__ float stage[2][5][64];
    __shared__ float red[4][64];
    __shared__ float denp[2];

    const int tid = threadIdx.x;
    const int cid = blockIdx.x;
    const int j   = cid & (NCHUNK - 1);
    const int bh  = cid >> 6;
    const int b   = bh >> 4;
    const int h   = bh & 15;
    const size_t base6 = ((size_t)b * LL + (size_t)j * CHUNK) * NPJ + (size_t)h * 64;

    const float* srcs[5] = { pj + base6,        pj + base6 + 1024, pj + base6 + 2048,
                             pj + base6 + 3072, pj + base6 + 4096 };

    const int  arr = tid >> 4;
    const int  ch  = tid & 15;
    const bool loader = (tid < 80);
    const float* mySrc = srcs[loader ? arr : 0] + ch * 4;
    const uint32_t mydst0 = (uint32_t)__cvta_generic_to_shared(&stage[0][0][0]) + (arr * 64 + ch * 4) * 4;
    const uint32_t mydst1 = mydst0 + 5 * 64 * 4;

    if (loader) cp16(mydst0, mySrc);
    asm volatile("cp.async.commit_group;\n");

    const int r = tid >> 5;
    const int c = tid & 31;
    float C0[16], C1[16];
#pragma unroll
    for (int i = 0; i < 16; i++) { C0[i] = 0.0f; C1[i] = 0.0f; }
    float nreg = 0.0f, cum = 1.0f;

    float* numIp = numI + (size_t)cid * 4096;
    float* qdp   = qd   + (size_t)cid * 4096;
    float* denIp = denI + (size_t)cid * 64;

    for (int t = 0; t < CHUNK; t++) {
        asm volatile("cp.async.wait_group 0;\n" ::: "memory");
        __syncthreads();
        const int cur = t & 1;

        if (t + 1 < CHUNK && loader)
            cp16(cur ? mydst0 : mydst1, mySrc + (size_t)(t + 1) * NPJ);
        asm volatile("cp.async.commit_group;\n");

        const float* S   = &stage[cur][0][0];
        const float* qs  = S;
        const float* ks  = S + 64;
        const float* vs  = S + 128;
        const float* is_ = S + 192;
        const float* fs  = S + 256;

        float v0 = vs[c], v1 = vs[c + 32];
        float pn0 = 0.0f, pn1 = 0.0f;

#define ROWOP(ff, qq, aa, idx) { float _a = (aa);                              \
        C0[idx] = fmaf((ff), C0[idx], _a * v0); pn0 = fmaf((qq), C0[idx], pn0);\
        C1[idx] = fmaf((ff), C1[idx], _a * v1); pn1 = fmaf((qq), C1[idx], pn1); }

#pragma unroll
        for (int dd = 0; dd < 16; dd += 4) {
            int d = r * 16 + dd;
            float4 f4 = *(const float4*)&fs[d];
            float4 q4 = *(const float4*)&qs[d];
            float4 i4 = *(const float4*)&is_[d];
            float4 k4 = *(const float4*)&ks[d];
            ROWOP(f4.x, q4.x, i4.x * k4.x, dd + 0);
            ROWOP(f4.y, q4.y, i4.y * k4.y, dd + 1);
            ROWOP(f4.z, q4.z, i4.z * k4.z, dd + 2);
            ROWOP(f4.w, q4.w, i4.w * k4.w, dd + 3);
        }
#undef ROWOP

        red[r][c]      = pn0;
        red[r][c + 32] = pn1;

        float qdv = 0.0f;
        if (tid < 64) {
            float a = is_[tid] * ks[tid];
            nreg = fmaf(fs[tid], nreg, a);
            cum *= fs[tid];
            qdv = qs[tid] * cum;
            float dp = qs[tid] * nreg;
#pragma unroll
            for (int o = 16; o; o >>= 1) dp += __shfl_xor_sync(0xffffffffu, dp, o);
            if ((tid & 31) == 0) denp[tid >> 5] = dp;
        }
        __syncthreads();

        if (tid < 64) {
            float num = red[0][tid] + red[1][tid] + red[2][tid] + red[3][tid];
            numIp[t * 64 + tid] = num;
            qdp[t * 64 + tid]   = qdv;
            if (tid == 0) denIp[t] = denp[0] + denp[1];
        }
    }

    float* dCp = dC + (size_t)cid * 4096;
#pragma unroll
    for (int dd = 0; dd < 16; dd++) {
        dCp[(r * 16 + dd) * 64 + c]      = C0[dd];
        dCp[(r * 16 + dd) * 64 + c + 32] = C1[dd];
    }
    if (tid < 64) {
        dN[(size_t)cid * 64 + tid] = nreg;
        G [(size_t)cid * 64 + tid] = cum;
    }
}

// ---------------------------------------------------------------------------
// Parallel carry (unchanged)
// ---------------------------------------------------------------------------
__global__ void __launch_bounds__(128)
chunk_carryP(const float* __restrict__ dC, const float* __restrict__ dN,
             const float* __restrict__ G,
             float* __restrict__ Cst, float* __restrict__ Nst)
{
    const int bh  = blockIdx.x;
    const int y   = blockIdx.y;
    const int tid = threadIdx.x;

    if (y < 8) {
        const int el = y * 512 + tid * 4;
        const int d  = el >> 6;
        float4 Cv = make_float4(0.f, 0.f, 0.f, 0.f);
        for (int j = 0; j < NCHUNK; j++) {
            const size_t cid = (size_t)bh * NCHUNK + j;
            *(float4*)&Cst[cid * 4096 + el] = Cv;
            const float g = G[cid * 64 + d];
            float4 dv = *(const float4*)&dC[cid * 4096 + el];
            Cv.x = fmaf(g, Cv.x, dv.x);
            Cv.y = fmaf(g, Cv.y, dv.y);
            Cv.z = fmaf(g, Cv.z, dv.z);
            Cv.w = fmaf(g, Cv.w, dv.w);
        }
    } else if (tid < 16) {
        const int e = tid * 4;
        float4 nv = make_float4(0.f, 0.f, 0.f, 0.f);
        for (int j = 0; j < NCHUNK; j++) {
            const size_t cid = (size_t)bh * NCHUNK + j;
            *(float4*)&Nst[cid * 64 + e] = nv;
            float4 gv = *(const float4*)&G[cid * 64 + e];
            float4 dn = *(const float4*)&dN[cid * 64 + e];
            nv.x = fmaf(gv.x, nv.x, dn.x);
            nv.y = fmaf(gv.y, nv.y, dn.y);
            nv.z = fmaf(gv.z, nv.z, dn.z);
            nv.w = fmaf(gv.w, nv.w, dn.w);
        }
    }
}

// ---------------------------------------------------------------------------
// Scan pass B (unchanged)
// ---------------------------------------------------------------------------
__global__ void __launch_bounds__(128)
chunk_inter(const float* __restrict__ pj,
            const float* __restrict__ Cst, const float* __restrict__ Nst,
            const float* __restrict__ numI, const float* __restrict__ qd,
            const float* __restrict__ denI,
            __half* __restrict__ hh)
{
    __shared__ float qs_[64 * 65];
    __shared__ float cs_[64 * 64];
    __shared__ float ns_[64], den_[64], dI_[64];

    const int tid = threadIdx.x;
    const int cid = blockIdx.x;
    const int j   = cid & (NCHUNK - 1);
    const int bh  = cid >> 6;
    const int b   = bh >> 4;
    const int h   = bh & 15;
    const size_t row0 = (size_t)b * LL + (size_t)j * CHUNK;

#pragma unroll
    for (int i = 0; i < 8; i++) {
        const int lin = tid + i * 128;
        const int t   = lin >> 4;
        const int dg  = (lin & 15) * 4;
        float4 qv = *(const float4*)&qd [(size_t)cid * 4096 + t * 64 + dg];
        qs_[t * 65 + dg + 0] = qv.x; qs_[t * 65 + dg + 1] = qv.y;
        qs_[t * 65 + dg + 2] = qv.z; qs_[t * 65 + dg + 3] = qv.w;
        *(float4*)&cs_[t * 64 + dg] = *(const float4*)&Cst[(size_t)cid * 4096 + t * 64 + dg];
    }
    if (tid < 64) {
        ns_[tid] = Nst [(size_t)cid * 64 + tid];
        dI_[tid] = denI[(size_t)cid * 64 + tid];
    }
    __syncthreads();

    if (tid < 64) {
        float s = dI_[tid];
#pragma unroll 8
        for (int d = 0; d < 64; d++) s = fmaf(qs_[tid * 65 + d], ns_[d], s);
        den_[tid] = fmaxf(s, 1.0f);
    }
    __syncthreads();

    const int tg = tid >> 3;
    const int eg = tid & 7;
    const int t0 = tg * 4;
    const int e0 = eg * 8;

    float acc[4][8];
#pragma unroll
    for (int a = 0; a < 4; a++) {
        float4 u0 = *(const float4*)&numI[(size_t)cid * 4096 + (t0 + a) * 64 + e0];
        float4 u1 = *(const float4*)&numI[(size_t)cid * 4096 + (t0 + a) * 64 + e0 + 4];
        acc[a][0] = u0.x; acc[a][1] = u0.y; acc[a][2] = u0.z; acc[a][3] = u0.w;
        acc[a][4] = u1.x; acc[a][5] = u1.y; acc[a][6] = u1.z; acc[a][7] = u1.w;
    }

#pragma unroll 4
    for (int d = 0; d < 64; d++) {
        float q0 = qs_[(t0 + 0) * 65 + d];
        float q1 = qs_[(t0 + 1) * 65 + d];
        float q2 = qs_[(t0 + 2) * 65 + d];
        float q3 = qs_[(t0 + 3) * 65 + d];
        float4 c0 = *(const float4*)&cs_[d * 64 + e0];
        float4 c1 = *(const float4*)&cs_[d * 64 + e0 + 4];
        float cv[8] = { c0.x, c0.y, c0.z, c0.w, c1.x, c1.y, c1.z, c1.w };
#pragma unroll
        for (int bb2 = 0; bb2 < 8; bb2++) {
            acc[0][bb2] = fmaf(q0, cv[bb2], acc[0][bb2]);
            acc[1][bb2] = fmaf(q1, cv[bb2], acc[1][bb2]);
            acc[2][bb2] = fmaf(q2, cv[bb2], acc[2][bb2]);
            acc[3][bb2] = fmaf(q3, cv[bb2], acc[3][bb2]);
        }
    }

#pragma unroll
    for (int a = 0; a < 4; a++) {
        const size_t grow = row0 + t0 + a;
        const size_t pb = grow * NPJ + (size_t)h * 64 + e0;
        float4 og0 = *(const float4*)&pj[pb + 5120];
        float4 og1 = *(const float4*)&pj[pb + 5124];
        float4 gt0 = *(const float4*)&pj[pb + 6144];
        float4 gt1 = *(const float4*)&pj[pb + 6148];
        float ogv[8] = { og0.x, og0.y, og0.z, og0.w, og1.x, og1.y, og1.z, og1.w };
        float gtv[8] = { gt0.x, gt0.y, gt0.z, gt0.w, gt1.x, gt1.y, gt1.z, gt1.w };
        const float dinv = 1.0f / den_[t0 + a];
        uint32_t packed[4];
#pragma unroll
        for (int p = 0; p < 4; p++) {
            float o0 = (acc[a][2*p]   * dinv) * ogv[2*p]   * (1.0f / (1.0f + expf(-gtv[2*p])));
            float o1 = (acc[a][2*p+1] * dinv) * ogv[2*p+1] * (1.0f / (1.0f + expf(-gtv[2*p+1])));
            packed[p] = packh(o0, o1);
        }
        *(uint4*)&hh[grow * 1024 + (size_t)h * 64 + e0] =
            make_uint4(packed[0], packed[1], packed[2], packed[3]);
    }
}

// ---------------------------------------------------------------------------
// Launch
// ---------------------------------------------------------------------------
extern "C" void kernel_launch(void* const* d_in, const int* in_sizes, int n_in,
                              void* d_out, int out_size)
{
    const float* x     = (const float*)d_in[0];
    const float* w_in  = (const float*)d_in[1];
    const float* w_q   = (const float*)d_in[2];
    const float* w_k   = (const float*)d_in[3];
    const float* w_v   = (const float*)d_in[4];
    const float* w_i   = (const float*)d_in[5];
    const float* b_i   = (const float*)d_in[6];
    const float* w_f   = (const float*)d_in[7];
    const float* b_f   = (const float*)d_in[8];
    const float* w_o   = (const float*)d_in[9];
    const float* b_o   = (const float*)d_in[10];
    const float* w_qn  = (const float*)d_in[11];
    const float* w_kn  = (const float*)d_in[12];
    const float* w_out = (const float*)d_in[13];
    float* out = (float*)d_out;

    float *pj, *dC, *dN, *G, *Cst, *Nst, *numI, *qdb, *denI;
    __half *xh, *hh, *wiT, *w6h, *w6l, *wff, *wof;
    cudaGetSymbolAddress((void**)&pj,   g_pj);
    cudaGetSymbolAddress((void**)&dC,   g_dC);
    cudaGetSymbolAddress((void**)&dN,   g_dN);
    cudaGetSymbolAddress((void**)&G,    g_G);
    cudaGetSymbolAddress((void**)&Cst,  g_Cst);
    cudaGetSymbolAddress((void**)&Nst,  g_Nst);
    cudaGetSymbolAddress((void**)&numI, g_numI);
    cudaGetSymbolAddress((void**)&qdb,  g_qd);
    cudaGetSymbolAddress((void**)&denI, g_denI);
    cudaGetSymbolAddress((void**)&xh,   g_xh);
    cudaGetSymbolAddress((void**)&hh,   g_hh);
    cudaGetSymbolAddress((void**)&wiT,  g_wiT);
    cudaGetSymbolAddress((void**)&w6h,  g_w6h);
    cudaGetSymbolAddress((void**)&w6l,  g_w6l);
    cudaGetSymbolAddress((void**)&wff,  g_wff);
    cudaGetSymbolAddress((void**)&wof,  g_wof);

    cudaFuncSetAttribute(gemm_f16<0,2>, cudaFuncAttributeMaxDynamicSharedMemorySize, GEMM_SMEM);
    cudaFuncSetAttribute(gemm_f16<1,1>, cudaFuncAttributeMaxDynamicSharedMemorySize, GEMM_SMEM);
    cudaFuncSetAttribute(gemm_f16<2,1>, cudaFuncAttributeMaxDynamicSharedMemorySize, GEMM_SMEM);

    // ---- pass 0: conversions ----
    transpose_wi<<<dim3(32, 32), 256>>>(w_in, wiT);
    cvt_all<<<1024, 256>>>((const float4*)x,
                           (const float4*)(w_in + (size_t)1024 * 1024),
                           (const float4*)w_q, (const float4*)w_k, (const float4*)w_v,
                           (const float4*)w_i, (const float4*)w_f, (const float4*)w_o,
                           (const float4*)w_out,
                           (uint2*)xh, (uint2*)(wff + (size_t)6144 * 1024),
                           (uint2*)w6h, (uint2*)w6l, (uint2*)wof);

    dim3 blk(128);

    // ---- Wfused[0:6144] = Wproj @ Wi_inner (persistent) ----
    gemm_f16<0,2><<<PGRID, blk, GEMM_SMEM>>>(
        w6h, w6l, 1024, wiT, nullptr, nullptr, nullptr, nullptr, nullptr,
        nullptr, 1024, wff, 48, 8);

    // ---- merged projections + gate from x: pj[8192,7168] (persistent) ----
    gemm_f16<1,1><<<PGRID, blk, GEMM_SMEM>>>(
        xh, nullptr, 1024, wff, w_qn, w_kn, b_i, b_f, b_o,
        pj, NPJ, nullptr, 64, 56);

    // ---- chunk-parallel scan ----
    chunk_fwdA  <<<NCID, 128>>>(pj, dC, dN, G, numI, qdb, denI);
    chunk_carryP<<<dim3(BB * NH, 9), 128>>>(dC, dN, G, Cst, Nst);
    chunk_inter <<<NCID, 128>>>(pj, Cst, Nst, numI, qdb, denI, hh);

    // ---- output projection (persistent) ----
    gemm_f16<2,1><<<PGRID, blk, GEMM_SMEM>>>(
        hh, nullptr, 1024, wof, nullptr, nullptr, nullptr, nullptr, nullptr,
        out, 1024, nullptr, 64, 8);
}

// round 15
// speedup vs baseline: 1.0464x; 1.0464x over previous
#include <cuda_runtime.h>
#include <cuda_fp16.h>
#include <math.h>
#include <stdint.h>

// Problem constants
#define BB   2
#define LL   4096
#define DIMD 1024
#define NH   16
#define HD   64
#define MROWS (BB * LL)          // 8192
#define KDIM 1024
#define CHUNK  64
#define NCHUNK (LL / CHUNK)      // 64
#define NCID   (BB * NH * NCHUNK) // 2048
#define NPJ  7168                // fused projection width: q|k|v|i|f|o|gate
#define PGRID 296                // persistent GEMM grid (2 CTAs/SM x 148)

// ---------------------------------------------------------------------------
// Scratch
// ---------------------------------------------------------------------------
__device__ float g_pj[(size_t)MROWS * NPJ];
__device__ __half g_xh  [(size_t)MROWS * 1024];
__device__ __half g_hh  [(size_t)MROWS * 1024];
__device__ __half g_wiT [(size_t)1024 * 1024];
__device__ __half g_w6h [(size_t)6 * 1024 * 1024];
__device__ __half g_w6l [(size_t)6 * 1024 * 1024];
__device__ __half g_wff [(size_t)NPJ * 1024];
__device__ __half g_wof [(size_t)1024 * 1024];
__device__ float g_dC  [(size_t)NCID * 4096];
__device__ float g_dN  [(size_t)NCID * 64];
__device__ float g_G   [(size_t)NCID * 64];
__device__ float g_Cst [(size_t)NCID * 4096];
__device__ float g_Nst [(size_t)NCID * 64];
__device__ float g_numI[(size_t)NCID * 4096];
__device__ float g_qd  [(size_t)NCID * 4096];
__device__ float g_denI[(size_t)NCID * 64];

// ---------------------------------------------------------------------------
// helpers
// ---------------------------------------------------------------------------
__device__ __forceinline__ uint32_t packh(float x, float y) {
    __half hx = __float2half_rn(x);
    __half hy = __float2half_rn(y);
    return (uint32_t)__half_as_ushort(hx) | ((uint32_t)__half_as_ushort(hy) << 16);
}
__device__ __forceinline__ uint32_t packhl(float x, float y) {
    __half hx = __float2half_rn(x);
    __half hy = __float2half_rn(y);
    return packh(x - __half2float(hx), y - __half2float(hy));
}
__device__ __forceinline__ void cp16(uint32_t s, const void* g)
{
    asm volatile("cp.async.ca.shared.global [%0], [%1], 16;\n" :: "r"(s), "l"(g));
}

#define LDSM_X4(r0, r1, r2, r3, addr) \
    asm volatile("ldmatrix.sync.aligned.m8n8.x4.shared.b16 {%0,%1,%2,%3}, [%4];" \
                 : "=r"(r0), "=r"(r1), "=r"(r2), "=r"(r3) : "r"(addr))

#define MMA_F16(d, a, b0, b1) \
    asm volatile("mma.sync.aligned.m16n8k16.row.col.f32.f16.f16.f32 " \
                 "{%0,%1,%2,%3}, {%4,%5,%6,%7}, {%8,%9}, {%0,%1,%2,%3};" \
                 : "+f"((d)[0]), "+f"((d)[1]), "+f"((d)[2]), "+f"((d)[3]) \
                 : "r"((a)[0]), "r"((a)[1]), "r"((a)[2]), "r"((a)[3]), \
                   "r"(b0), "r"(b1))

// ---------------------------------------------------------------------------
// Pass 0: fused conversion mega-kernel
// ---------------------------------------------------------------------------
#define R0N 2097152
#define R1N 262144
#define R2N 1572864
#define R3N 262144
#define RTOT (R0N + R1N + R2N + R3N)

__global__ void cvt_all(const float4* __restrict__ x,
                        const float4* __restrict__ wgate,
                        const float4* __restrict__ w0, const float4* __restrict__ w1,
                        const float4* __restrict__ w2, const float4* __restrict__ w3,
                        const float4* __restrict__ w4, const float4* __restrict__ w5,
                        const float4* __restrict__ wout,
                        uint2* __restrict__ xh, uint2* __restrict__ wffgate,
                        uint2* __restrict__ w6h, uint2* __restrict__ w6l,
                        uint2* __restrict__ wof)
{
    for (int idx = blockIdx.x * 256 + threadIdx.x; idx < RTOT; idx += gridDim.x * 256) {
        if (idx < R0N) {
            float4 v = x[idx];
            xh[idx] = make_uint2(packh(v.x, v.y), packh(v.z, v.w));
        } else if (idx < R0N + R1N) {
            const int i = idx - R0N;
            float4 v = wgate[i];
            wffgate[i] = make_uint2(packh(v.x, v.y), packh(v.z, v.w));
        } else if (idx < R0N + R1N + R2N) {
            const int l = idx - R0N - R1N;
            const int which = l >> 18;
            const int i = l & 262143;
            const float4* s;
            switch (which) {
                case 0: s = w0; break; case 1: s = w1; break; case 2: s = w2; break;
                case 3: s = w3; break; case 4: s = w4; break; default: s = w5; break;
            }
            float4 v = s[i];
            w6h[l] = make_uint2(packh(v.x, v.y),  packh(v.z, v.w));
            w6l[l] = make_uint2(packhl(v.x, v.y), packhl(v.z, v.w));
        } else {
            const int i = idx - R0N - R1N - R2N;
            float4 v = wout[i];
            wof[i] = make_uint2(packh(v.x, v.y), packh(v.z, v.w));
        }
    }
}

__global__ void transpose_wi(const float* __restrict__ w, __half* __restrict__ wt)
{
    __shared__ float tile[32][33];
    const int bx = blockIdx.x * 32, by = blockIdx.y * 32;
    const int tx = threadIdx.x & 31, ty = threadIdx.x >> 5;
#pragma unroll
    for (int dy = 0; dy < 32; dy += 8)
        tile[ty + dy][tx] = w[(size_t)(by + ty + dy) * 1024 + bx + tx];
    __syncthreads();
#pragma unroll
    for (int dy = 0; dy < 32; dy += 8)
        wt[(size_t)(bx + ty + dy) * 1024 + by + tx] = __float2half_rn(tile[tx][ty + dy]);
}

// ---------------------------------------------------------------------------
// Persistent cp.async fp16 GEMM, v2: all tile addressing hoisted out of the
// k-loop. Each CTA walks tiles bid + i*PGRID; steps 29..31 of tile t prefetch
// stages 0..2 of tile t+1 through pre-computed next-tile pointers (no drain,
// no division in the hot path). Buffer index is pure s-based (32 % 4 == 0).
// TERMS: 2 = split A (hi+lo); 1 = single fp16 A.
// MODE:  0 = fp16 output Chh; 1 = projections; 2 = fp32 C.
// ---------------------------------------------------------------------------
#define STAGES 4
#define SECB   8192
#define STAGEB (3 * SECB)
#define GEMM_SMEM (STAGES * STAGEB)

template <int MODE, int TERMS>
__global__ void __launch_bounds__(128, 2)
gemm_f16(const __half* __restrict__ Ah, const __half* __restrict__ Al, int lda,
         const __half* __restrict__ B,
         const float* __restrict__ q0, const float* __restrict__ q1,
         const float* __restrict__ q2, const float* __restrict__ q3,
         const float* __restrict__ q4,
         float* __restrict__ C, int ldc,
         __half* __restrict__ Chh,
         int MT, int NT)
{
    extern __shared__ __align__(128) char smem[];
    const uint32_t sbase = (uint32_t)__cvta_generic_to_shared(smem);

    const int tid  = threadIdx.x;
    const int w    = tid >> 5;
    const int lane = tid & 31;
    const int wm   = w & 1;
    const int wn   = w >> 1;

    const int tiles = MT * NT;
    const int bid   = (int)blockIdx.x;
    const int nt    = (tiles - bid + PGRID - 1) / PGRID;
    if (nt <= 0) return;

    // loader: ready pointers + k0 + buffer. Identical inner arithmetic to R13.
    auto load_st = [&](const __half* Ap, const __half* Alp, const __half* Bp,
                       int k0, int buf) {
        const uint32_t db = sbase + (uint32_t)(buf * STAGEB);
        const int NCH = (TERMS == 2) ? 12 : 8;
#pragma unroll
        for (int i = 0; i < NCH; i++) {
            const int ci  = tid + i * 128;
            const int s2  = ci >> 9;
            const int r   = (ci >> 2) & 127;
            const int kq  = ci & 3;
            const __half* gp;
            uint32_t secoff;
            if (TERMS == 2) {
                if      (s2 == 0) { gp = Ap  + (size_t)r * lda; secoff = 0; }
                else if (s2 == 1) { gp = Alp + (size_t)r * lda; secoff = SECB; }
                else              { gp = Bp  + (size_t)r * KDIM; secoff = 2 * SECB; }
            } else {
                if (s2 == 0) { gp = Ap + (size_t)r * lda; secoff = 0; }
                else         { gp = Bp + (size_t)r * KDIM; secoff = 2 * SECB; }
            }
            gp += k0 + kq * 8;
            const uint32_t d = db + secoff + (uint32_t)(r * 64 + ((kq * 16) ^ ((r * 8) & 0x30)));
            cp16(d, gp);
        }
    };

    // tile pointer setup (division happens only here, once per tile)
    auto tile_ptrs = [&](int tile, const __half*& A_, const __half*& Al_,
                         const __half*& B_, int& m0_, int& n0_) {
        const int mtl = tile / NT;
        const int ntl = tile - mtl * NT;
        m0_ = mtl * 128;
        n0_ = ntl * 128;
        A_  = Ah + (size_t)m0_ * lda;
        Al_ = (TERMS == 2) ? (Al + (size_t)m0_ * lda) : nullptr;
        B_  = B + (size_t)n0_ * KDIM;
    };

    // ldmatrix per-lane addressing (SW64)
    const int a_r  = (lane & 7) + ((lane >> 3) & 1) * 8;
    const int ak2  = ((lane >> 4) & 1) * 16;
    const uint32_t axr = (uint32_t)((a_r << 3) & 0x30);
    const int g_   = lane >> 3;
    const int b_r  = ((g_ >> 1) * 8) + (lane & 7);
    const int bk2  = (g_ & 1) * 16;
    const uint32_t bxr = (uint32_t)((b_r << 3) & 0x30);

    uint32_t aoff[4], boff[4];
#pragma unroll
    for (int mi = 0; mi < 4; mi++) aoff[mi] = (uint32_t)((wm * 64 + mi * 16 + a_r) * 64);
#pragma unroll
    for (int gi = 0; gi < 4; gi++) boff[gi] = (uint32_t)(2 * SECB + (wn * 64 + gi * 16 + b_r) * 64);

    const int qr = lane >> 2;
    const int qc = (lane & 3) * 2;

    // current tile
    const __half *Ac, *Alc, *Bc;
    int m0c, n0c;
    tile_ptrs(bid, Ac, Alc, Bc, m0c, n0c);

    // prologue: stages 0..2 of tile 0 -> bufs 0,1,2
    load_st(Ac, Alc, Bc, 0,  0); asm volatile("cp.async.commit_group;\n");
    load_st(Ac, Alc, Bc, 32, 1); asm volatile("cp.async.commit_group;\n");
    load_st(Ac, Alc, Bc, 64, 2); asm volatile("cp.async.commit_group;\n");

    for (int ti = 0; ti < nt; ti++) {
        const bool haveNext = (ti + 1 < nt);
        const __half *An = nullptr, *Aln = nullptr, *Bn = nullptr;
        int m0n = 0, n0n = 0;
        if (haveNext) tile_ptrs(bid + (ti + 1) * PGRID, An, Aln, Bn, m0n, n0n);

        float acc[4][8][4] = {};

        for (int s = 0; s < 32; s++) {
            asm volatile("cp.async.wait_group 2;\n" ::: "memory");
            __syncthreads();
            const int buf = (s + 3) & 3;
            if (s < 29)         load_st(Ac, Alc, Bc, (s + 3) * 32, buf);
            else if (haveNext)  load_st(An, Aln, Bn, (s - 29) * 32, buf);
            asm volatile("cp.async.commit_group;\n");

            const uint32_t bb = sbase + (uint32_t)((s & 3) * STAGEB);
#pragma unroll
            for (int kb = 0; kb < 2; kb++) {
                const uint32_t kx = (uint32_t)(kb * 32);
                uint32_t Bf[4][4];
#pragma unroll
                for (int gi = 0; gi < 4; gi++) {
                    const uint32_t ba = bb + boff[gi] + ((kx + bk2) ^ bxr);
                    LDSM_X4(Bf[gi][0], Bf[gi][1], Bf[gi][2], Bf[gi][3], ba);
                }
                {
                    uint32_t Af[4][4];
#pragma unroll
                    for (int mi = 0; mi < 4; mi++) {
                        const uint32_t aa = bb + aoff[mi] + ((kx + ak2) ^ axr);
                        LDSM_X4(Af[mi][0], Af[mi][1], Af[mi][2], Af[mi][3], aa);
                    }
#pragma unroll
                    for (int gi = 0; gi < 4; gi++)
#pragma unroll
                        for (int mi = 0; mi < 4; mi++)
#pragma unroll
                            for (int hf = 0; hf < 2; hf++)
                                MMA_F16(acc[mi][gi * 2 + hf], Af[mi], Bf[gi][2 * hf], Bf[gi][2 * hf + 1]);
                }
                if (TERMS == 2) {
                    uint32_t Af[4][4];
#pragma unroll
                    for (int mi = 0; mi < 4; mi++) {
                        const uint32_t aa = bb + aoff[mi] + ((kx + ak2) ^ axr) + SECB;
                        LDSM_X4(Af[mi][0], Af[mi][1], Af[mi][2], Af[mi][3], aa);
                    }
#pragma unroll
                    for (int gi = 0; gi < 4; gi++)
#pragma unroll
                        for (int mi = 0; mi < 4; mi++)
#pragma unroll
                            for (int hf = 0; hf < 2; hf++)
                                MMA_F16(acc[mi][gi * 2 + hf], Af[mi], Bf[gi][2 * hf], Bf[gi][2 * hf + 1]);
                }
            }
        }

        // ---- epilogue for this tile ----
        const int seg = n0c >> 10;

        if (MODE == 1 && seg < 2) {
            const float* wn_ = (seg == 0) ? q0 : q1;
#pragma unroll
            for (int mi = 0; mi < 4; mi++)
#pragma unroll
                for (int rh = 0; rh < 2; rh++) {
                    float ss = 0.0f;
#pragma unroll
                    for (int tti = 0; tti < 8; tti++) {
                        float a = acc[mi][tti][2 * rh], b2 = acc[mi][tti][2 * rh + 1];
                        ss += a * a + b2 * b2;
                    }
                    ss += __shfl_xor_sync(0xffffffffu, ss, 1);
                    ss += __shfl_xor_sync(0xffffffffu, ss, 2);
                    const float sc = rsqrtf(ss * (1.0f / 64.0f) + 1e-6f);
#pragma unroll
                    for (int tti = 0; tti < 8; tti++) {
                        acc[mi][tti][2 * rh]     *= sc * wn_[tti * 8 + qc];
                        acc[mi][tti][2 * rh + 1] *= sc * wn_[tti * 8 + qc + 1];
                    }
                }
        }

#pragma unroll
        for (int mi = 0; mi < 4; mi++) {
#pragma unroll
            for (int tti = 0; tti < 8; tti++) {
                const int col = n0c + wn * 64 + tti * 8 + qc;
                float b0 = 0.f, b1 = 0.f;
                if (MODE == 1 && seg >= 3 && seg <= 5) {
                    const float* bp = (seg == 3) ? q2 : (seg == 4) ? q3 : q4;
                    const int cs = col & 1023;
                    b0 = bp[cs]; b1 = bp[cs + 1];
                }
#pragma unroll
                for (int rh = 0; rh < 2; rh++) {
                    const int row = m0c + wm * 64 + mi * 16 + rh * 8 + qr;
                    float x0 = acc[mi][tti][2 * rh + 0];
                    float x1 = acc[mi][tti][2 * rh + 1];
                    if (MODE == 1) {
                        if (seg == 3)                  { x0 = expf(x0 + b0); x1 = expf(x1 + b1); }
                        else if (seg == 4 || seg == 5) { x0 = 1.0f / (1.0f + expf(-(x0 + b0)));
                                                         x1 = 1.0f / (1.0f + expf(-(x1 + b1))); }
                    }
                    if (MODE == 0) {
                        *(uint32_t*)&Chh[(size_t)row * ldc + col] = packh(x0, x1);
                    } else {
                        *(float2*)&C[(size_t)row * ldc + col] = make_float2(x0, x1);
                    }
                }
            }
        }

        Ac = An; Alc = Aln; Bc = Bn; m0c = m0n; n0c = n0n;
    }
}

// ---------------------------------------------------------------------------
// Scan pass A (unchanged)
// ---------------------------------------------------------------------------
__global__ void __launch_bounds__(128, 4)
chunk_fwdA(const float* __restrict__ pj,
           float* __restrict__ dC, float* __restrict__ dN, float* __restrict__ G,
           float* __restrict__ numI, float* __restrict__ qd, float* __restrict__ denI)
{
    __shared__ float stage[2][5][64];
    __shared__ float red[4][64];
    __shared__ float denp[2];

    const int tid = threadIdx.x;
    const int cid = blockIdx.x;
    const int j   = cid & (NCHUNK - 1);
    const int bh  = cid >> 6;
    const int b   = bh >> 4;
    const int h   = bh & 15;
    const size_t base6 = ((size_t)b * LL + (size_t)j * CHUNK) * NPJ + (size_t)h * 64;

    const float* srcs[5] = { pj + base6,        pj + base6 + 1024, pj + base6 + 2048,
                             pj + base6 + 3072, pj + base6 + 4096 };

    const int  arr = tid >> 4;
    const int  ch  = tid & 15;
    const bool loader = (tid < 80);
    const float* mySrc = srcs[loader ? arr : 0] + ch * 4;
    const uint32_t mydst0 = (uint32_t)__cvta_generic_to_shared(&stage[0][0][0]) + (arr * 64 + ch * 4) * 4;
    const uint32_t mydst1 = mydst0 + 5 * 64 * 4;

    if (loader) cp16(mydst0, mySrc);
    asm volatile("cp.async.commit_group;\n");

    const int r = tid >> 5;
    const int c = tid & 31;
    float C0[16], C1[16];
#pragma unroll
    for (int i = 0; i < 16; i++) { C0[i] = 0.0f; C1[i] = 0.0f; }
    float nreg = 0.0f, cum = 1.0f;

    float* numIp = numI + (size_t)cid * 4096;
    float* qdp   = qd   + (size_t)cid * 4096;
    float* denIp = denI + (size_t)cid * 64;

    for (int t = 0; t < CHUNK; t++) {
        asm volatile("cp.async.wait_group 0;\n" ::: "memory");
        __syncthreads();
        const int cur = t & 1;

        if (t + 1 < CHUNK && loader)
            cp16(cur ? mydst0 : mydst1, mySrc + (size_t)(t + 1) * NPJ);
        asm volatile("cp.async.commit_group;\n");

        const float* S   = &stage[cur][0][0];
        const float* qs  = S;
        const float* ks  = S + 64;
        const float* vs  = S + 128;
        const float* is_ = S + 192;
        const float* fs  = S + 256;

        float v0 = vs[c], v1 = vs[c + 32];
        float pn0 = 0.0f, pn1 = 0.0f;

#define ROWOP(ff, qq, aa, idx) { float _a = (aa);                              \
        C0[idx] = fmaf((ff), C0[idx], _a * v0); pn0 = fmaf((qq), C0[idx], pn0);\
        C1[idx] = fmaf((ff), C1[idx], _a * v1); pn1 = fmaf((qq), C1[idx], pn1); }

#pragma unroll
        for (int dd = 0; dd < 16; dd += 4) {
            int d = r * 16 + dd;
            float4 f4 = *(const float4*)&fs[d];
            float4 q4 = *(const float4*)&qs[d];
            float4 i4 = *(const float4*)&is_[d];
            float4 k4 = *(const float4*)&ks[d];
            ROWOP(f4.x, q4.x, i4.x * k4.x, dd + 0);
            ROWOP(f4.y, q4.y, i4.y * k4.y, dd + 1);
            ROWOP(f4.z, q4.z, i4.z * k4.z, dd + 2);
            ROWOP(f4.w, q4.w, i4.w * k4.w, dd + 3);
        }
#undef ROWOP

        red[r][c]      = pn0;
        red[r][c + 32] = pn1;

        float qdv = 0.0f;
        if (tid < 64) {
            float a = is_[tid] * ks[tid];
            nreg = fmaf(fs[tid], nreg, a);
            cum *= fs[tid];
            qdv = qs[tid] * cum;
            float dp = qs[tid] * nreg;
#pragma unroll
            for (int o = 16; o; o >>= 1) dp += __shfl_xor_sync(0xffffffffu, dp, o);
            if ((tid & 31) == 0) denp[tid >> 5] = dp;
        }
        __syncthreads();

        if (tid < 64) {
            float num = red[0][tid] + red[1][tid] + red[2][tid] + red[3][tid];
            numIp[t * 64 + tid] = num;
            qdp[t * 64 + tid]   = qdv;
            if (tid == 0) denIp[t] = denp[0] + denp[1];
        }
    }

    float* dCp = dC + (size_t)cid * 4096;
#pragma unroll
    for (int dd = 0; dd < 16; dd++) {
        dCp[(r * 16 + dd) * 64 + c]      = C0[dd];
        dCp[(r * 16 + dd) * 64 + c + 32] = C1[dd];
    }
    if (tid < 64) {
        dN[(size_t)cid * 64 + tid] = nreg;
        G [(size_t)cid * 64 + tid] = cum;
    }
}

// ---------------------------------------------------------------------------
// Parallel carry (unchanged)
// ---------------------------------------------------------------------------
__global__ void __launch_bounds__(128)
chunk_carryP(const float* __restrict__ dC, const float* __restrict__ dN,
             const float* __restrict__ G,
             float* __restrict__ Cst, float* __restrict__ Nst)
{
    const int bh  = blockIdx.x;
    const int y   = blockIdx.y;
    const int tid = threadIdx.x;

    if (y < 8) {
        const int el = y * 512 + tid * 4;
        const int d  = el >> 6;
        float4 Cv = make_float4(0.f, 0.f, 0.f, 0.f);
        for (int j = 0; j < NCHUNK; j++) {
            const size_t cid = (size_t)bh * NCHUNK + j;
            *(float4*)&Cst[cid * 4096 + el] = Cv;
            const float g = G[cid * 64 + d];
            float4 dv = *(const float4*)&dC[cid * 4096 + el];
            Cv.x = fmaf(g, Cv.x, dv.x);
            Cv.y = fmaf(g, Cv.y, dv.y);
            Cv.z = fmaf(g, Cv.z, dv.z);
            Cv.w = fmaf(g, Cv.w, dv.w);
        }
    } else if (tid < 16) {
        const int e = tid * 4;
        float4 nv = make_float4(0.f, 0.f, 0.f, 0.f);
        for (int j = 0; j < NCHUNK; j++) {
            const size_t cid = (size_t)bh * NCHUNK + j;
            *(float4*)&Nst[cid * 64 + e] = nv;
            float4 gv = *(const float4*)&G[cid * 64 + e];
            float4 dn = *(const float4*)&dN[cid * 64 + e];
            nv.x = fmaf(gv.x, nv.x, dn.x);
            nv.y = fmaf(gv.y, nv.y, dn.y);
            nv.z = fmaf(gv.z, nv.z, dn.z);
            nv.w = fmaf(gv.w, nv.w, dn.w);
        }
    }
}

// ---------------------------------------------------------------------------
// Scan pass B (unchanged)
// ---------------------------------------------------------------------------
__global__ void __launch_bounds__(128)
chunk_inter(const float* __restrict__ pj,
            const float* __restrict__ Cst, const float* __restrict__ Nst,
            const float* __restrict__ numI, const float* __restrict__ qd,
            const float* __restrict__ denI,
            __half* __restrict__ hh)
{
    __shared__ float qs_[64 * 65];
    __shared__ float cs_[64 * 64];
    __shared__ float ns_[64], den_[64], dI_[64];

    const int tid = threadIdx.x;
    const int cid = blockIdx.x;
    const int j   = cid & (NCHUNK - 1);
    const int bh  = cid >> 6;
    const int b   = bh >> 4;
    const int h   = bh & 15;
    const size_t row0 = (size_t)b * LL + (size_t)j * CHUNK;

#pragma unroll
    for (int i = 0; i < 8; i++) {
        const int lin = tid + i * 128;
        const int t   = lin >> 4;
        const int dg  = (lin & 15) * 4;
        float4 qv = *(const float4*)&qd [(size_t)cid * 4096 + t * 64 + dg];
        qs_[t * 65 + dg + 0] = qv.x; qs_[t * 65 + dg + 1] = qv.y;
        qs_[t * 65 + dg + 2] = qv.z; qs_[t * 65 + dg + 3] = qv.w;
        *(float4*)&cs_[t * 64 + dg] = *(const float4*)&Cst[(size_t)cid * 4096 + t * 64 + dg];
    }
    if (tid < 64) {
        ns_[tid] = Nst [(size_t)cid * 64 + tid];
        dI_[tid] = denI[(size_t)cid * 64 + tid];
    }
    __syncthreads();

    if (tid < 64) {
        float s = dI_[tid];
#pragma unroll 8
        for (int d = 0; d < 64; d++) s = fmaf(qs_[tid * 65 + d], ns_[d], s);
        den_[tid] = fmaxf(s, 1.0f);
    }
    __syncthreads();

    const int tg = tid >> 3;
    const int eg = tid & 7;
    const int t0 = tg * 4;
    const int e0 = eg * 8;

    float acc[4][8];
#pragma unroll
    for (int a = 0; a < 4; a++) {
        float4 u0 = *(const float4*)&numI[(size_t)cid * 4096 + (t0 + a) * 64 + e0];
        float4 u1 = *(const float4*)&numI[(size_t)cid * 4096 + (t0 + a) * 64 + e0 + 4];
        acc[a][0] = u0.x; acc[a][1] = u0.y; acc[a][2] = u0.z; acc[a][3] = u0.w;
        acc[a][4] = u1.x; acc[a][5] = u1.y; acc[a][6] = u1.z; acc[a][7] = u1.w;
    }

#pragma unroll 4
    for (int d = 0; d < 64; d++) {
        float q0 = qs_[(t0 + 0) * 65 + d];
        float q1 = qs_[(t0 + 1) * 65 + d];
        float q2 = qs_[(t0 + 2) * 65 + d];
        float q3 = qs_[(t0 + 3) * 65 + d];
        float4 c0 = *(const float4*)&cs_[d * 64 + e0];
        float4 c1 = *(const float4*)&cs_[d * 64 + e0 + 4];
        float cv[8] = { c0.x, c0.y, c0.z, c0.w, c1.x, c1.y, c1.z, c1.w };
#pragma unroll
        for (int bb2 = 0; bb2 < 8; bb2++) {
            acc[0][bb2] = fmaf(q0, cv[bb2], acc[0][bb2]);
            acc[1][bb2] = fmaf(q1, cv[bb2], acc[1][bb2]);
            acc[2][bb2] = fmaf(q2, cv[bb2], acc[2][bb2]);
            acc[3][bb2] = fmaf(q3, cv[bb2], acc[3][bb2]);
        }
    }

#pragma unroll
    for (int a = 0; a < 4; a++) {
        const size_t grow = row0 + t0 + a;
        const size_t pb = grow * NPJ + (size_t)h * 64 + e0;
        float4 og0 = *(const float4*)&pj[pb + 5120];
        float4 og1 = *(const float4*)&pj[pb + 5124];
        float4 gt0 = *(const float4*)&pj[pb + 6144];
        float4 gt1 = *(const float4*)&pj[pb + 6148];
        float ogv[8] = { og0.x, og0.y, og0.z, og0.w, og1.x, og1.y, og1.z, og1.w };
        float gtv[8] = { gt0.x, gt0.y, gt0.z, gt0.w, gt1.x, gt1.y, gt1.z, gt1.w };
        const float dinv = 1.0f / den_[t0 + a];
        uint32_t packed[4];
#pragma unroll
        for (int p = 0; p < 4; p++) {
            float o0 = (acc[a][2*p]   * dinv) * ogv[2*p]   * (1.0f / (1.0f + expf(-gtv[2*p])));
            float o1 = (acc[a][2*p+1] * dinv) * ogv[2*p+1] * (1.0f / (1.0f + expf(-gtv[2*p+1])));
            packed[p] = packh(o0, o1);
        }
        *(uint4*)&hh[grow * 1024 + (size_t)h * 64 + e0] =
            make_uint4(packed[0], packed[1], packed[2], packed[3]);
    }
}

// ---------------------------------------------------------------------------
// Launch
// ---------------------------------------------------------------------------
extern "C" void kernel_launch(void* const* d_in, const int* in_sizes, int n_in,
                              void* d_out, int out_size)
{
    const float* x     = (const float*)d_in[0];
    const float* w_in  = (const float*)d_in[1];
    const float* w_q   = (const float*)d_in[2];
    const float* w_k   = (const float*)d_in[3];
    const float* w_v   = (const float*)d_in[4];
    const float* w_i   = (const float*)d_in[5];
    const float* b_i   = (const float*)d_in[6];
    const float* w_f   = (const float*)d_in[7];
    const float* b_f   = (const float*)d_in[8];
    const float* w_o   = (const float*)d_in[9];
    const float* b_o   = (const float*)d_in[10];
    const float* w_qn  = (const float*)d_in[11];
    const float* w_kn  = (const float*)d_in[12];
    const float* w_out = (const float*)d_in[13];
    float* out = (float*)d_out;

    float *pj, *dC, *dN, *G, *Cst, *Nst, *numI, *qdb, *denI;
    __half *xh, *hh, *wiT, *w6h, *w6l, *wff, *wof;
    cudaGetSymbolAddress((void**)&pj,   g_pj);
    cudaGetSymbolAddress((void**)&dC,   g_dC);
    cudaGetSymbolAddress((void**)&dN,   g_dN);
    cudaGetSymbolAddress((void**)&G,    g_G);
    cudaGetSymbolAddress((void**)&Cst,  g_Cst);
    cudaGetSymbolAddress((void**)&Nst,  g_Nst);
    cudaGetSymbolAddress((void**)&numI, g_numI);
    cudaGetSymbolAddress((void**)&qdb,  g_qd);
    cudaGetSymbolAddress((void**)&denI, g_denI);
    cudaGetSymbolAddress((void**)&xh,   g_xh);
    cudaGetSymbolAddress((void**)&hh,   g_hh);
    cudaGetSymbolAddress((void**)&wiT,  g_wiT);
    cudaGetSymbolAddress((void**)&w6h,  g_w6h);
    cudaGetSymbolAddress((void**)&w6l,  g_w6l);
    cudaGetSymbolAddress((void**)&wff,  g_wff);
    cudaGetSymbolAddress((void**)&wof,  g_wof);

    cudaFuncSetAttribute(gemm_f16<0,2>, cudaFuncAttributeMaxDynamicSharedMemorySize, GEMM_SMEM);
    cudaFuncSetAttribute(gemm_f16<1,1>, cudaFuncAttributeMaxDynamicSharedMemorySize, GEMM_SMEM);
    cudaFuncSetAttribute(gemm_f16<2,1>, cudaFuncAttributeMaxDynamicSharedMemorySize, GEMM_SMEM);

    // ---- pass 0: conversions ----
    transpose_wi<<<dim3(32, 32), 256>>>(w_in, wiT);
    cvt_all<<<1024, 256>>>((const float4*)x,
                           (const float4*)(w_in + (size_t)1024 * 1024),
                           (const float4*)w_q, (const float4*)w_k, (const float4*)w_v,
                           (const float4*)w_i, (const float4*)w_f, (const float4*)w_o,
                           (const float4*)w_out,
                           (uint2*)xh, (uint2*)(wff + (size_t)6144 * 1024),
                           (uint2*)w6h, (uint2*)w6l, (uint2*)wof);

    dim3 blk(128);

    // ---- Wfused[0:6144] = Wproj @ Wi_inner (persistent) ----
    gemm_f16<0,2><<<PGRID, blk, GEMM_SMEM>>>(
        w6h, w6l, 1024, wiT, nullptr, nullptr, nullptr, nullptr, nullptr,
        nullptr, 1024, wff, 48, 8);

    // ---- merged projections + gate from x: pj[8192,7168] (persistent) ----
    gemm_f16<1,1><<<PGRID, blk, GEMM_SMEM>>>(
        xh, nullptr, 1024, wff, w_qn, w_kn, b_i, b_f, b_o,
        pj, NPJ, nullptr, 64, 56);

    // ---- chunk-parallel scan ----
    chunk_fwdA  <<<NCID, 128>>>(pj, dC, dN, G, numI, qdb, denI);
    chunk_carryP<<<dim3(BB * NH, 9), 128>>>(dC, dN, G, Cst, Nst);
    chunk_inter <<<NCID, 128>>>(pj, Cst, Nst, numI, qdb, denI, hh);

    // ---- output projection (persistent) ----
    gemm_f16<2,1><<<PGRID, blk, GEMM_SMEM>>>(
        hh, nullptr, 1024, wof, nullptr, nullptr, nullptr, nullptr, nullptr,
        out, 1024, nullptr, 64, 8);
}

// round 16
// speedup vs baseline: 1.0643x; 1.0171x over previous
#include <cuda_runtime.h>
#include <cuda_fp16.h>
#include <math.h>
#include <stdint.h>

// Problem constants
#define BB   2
#define LL   4096
#define DIMD 1024
#define NH   16
#define HD   64
#define MROWS (BB * LL)          // 8192
#define KDIM 1024
#define CHUNK  64
#define NCHUNK (LL / CHUNK)      // 64
#define NCID   (BB * NH * NCHUNK) // 2048
#define NPJ  7168                // fused projection width: q|k|v|i|f|o|gate

// ---------------------------------------------------------------------------
// Scratch
// ---------------------------------------------------------------------------
__device__ float g_pj[(size_t)MROWS * NPJ];
__device__ __half g_xh  [(size_t)MROWS * 1024];
__device__ __half g_hh  [(size_t)MROWS * 1024];
__device__ __half g_wiT [(size_t)1024 * 1024];
__device__ __half g_w6h [(size_t)6 * 1024 * 1024];
__device__ __half g_w6l [(size_t)6 * 1024 * 1024];
__device__ __half g_wff [(size_t)NPJ * 1024];
__device__ __half g_wof [(size_t)1024 * 1024];
__device__ float g_dC  [(size_t)NCID * 4096];
__device__ float g_dN  [(size_t)NCID * 64];
__device__ float g_G   [(size_t)NCID * 64];
__device__ float g_Cst [(size_t)NCID * 4096];
__device__ float g_Nst [(size_t)NCID * 64];
__device__ float g_numI[(size_t)NCID * 4096];
__device__ float g_qd  [(size_t)NCID * 4096];
__device__ float g_denI[(size_t)NCID * 64];

// ---------------------------------------------------------------------------
// helpers
// ---------------------------------------------------------------------------
__device__ __forceinline__ uint32_t packh(float x, float y) {
    __half hx = __float2half_rn(x);
    __half hy = __float2half_rn(y);
    return (uint32_t)__half_as_ushort(hx) | ((uint32_t)__half_as_ushort(hy) << 16);
}
__device__ __forceinline__ uint32_t packhl(float x, float y) {
    __half hx = __float2half_rn(x);
    __half hy = __float2half_rn(y);
    return packh(x - __half2float(hx), y - __half2float(hy));
}
__device__ __forceinline__ void cp16(uint32_t s, const void* g)
{
    asm volatile("cp.async.ca.shared.global [%0], [%1], 16;\n" :: "r"(s), "l"(g));
}

#define LDSM_X4(r0, r1, r2, r3, addr) \
    asm volatile("ldmatrix.sync.aligned.m8n8.x4.shared.b16 {%0,%1,%2,%3}, [%4];" \
                 : "=r"(r0), "=r"(r1), "=r"(r2), "=r"(r3) : "r"(addr))

#define MMA_F16(d, a, b0, b1) \
    asm volatile("mma.sync.aligned.m16n8k16.row.col.f32.f16.f16.f32 " \
                 "{%0,%1,%2,%3}, {%4,%5,%6,%7}, {%8,%9}, {%0,%1,%2,%3};" \
                 : "+f"((d)[0]), "+f"((d)[1]), "+f"((d)[2]), "+f"((d)[3]) \
                 : "r"((a)[0]), "r"((a)[1]), "r"((a)[2]), "r"((a)[3]), \
                   "r"(b0), "r"(b1))

// ---------------------------------------------------------------------------
// Pass 0: fused conversion mega-kernel (grid-stride over 4 regions)
// ---------------------------------------------------------------------------
#define R0N 2097152
#define R1N 262144
#define R2N 1572864
#define R3N 262144
#define RTOT (R0N + R1N + R2N + R3N)

__global__ void cvt_all(const float4* __restrict__ x,
                        const float4* __restrict__ wgate,
                        const float4* __restrict__ w0, const float4* __restrict__ w1,
                        const float4* __restrict__ w2, const float4* __restrict__ w3,
                        const float4* __restrict__ w4, const float4* __restrict__ w5,
                        const float4* __restrict__ wout,
                        uint2* __restrict__ xh, uint2* __restrict__ wffgate,
                        uint2* __restrict__ w6h, uint2* __restrict__ w6l,
                        uint2* __restrict__ wof)
{
    for (int idx = blockIdx.x * 256 + threadIdx.x; idx < RTOT; idx += gridDim.x * 256) {
        if (idx < R0N) {
            float4 v = x[idx];
            xh[idx] = make_uint2(packh(v.x, v.y), packh(v.z, v.w));
        } else if (idx < R0N + R1N) {
            const int i = idx - R0N;
            float4 v = wgate[i];
            wffgate[i] = make_uint2(packh(v.x, v.y), packh(v.z, v.w));
        } else if (idx < R0N + R1N + R2N) {
            const int l = idx - R0N - R1N;
            const int which = l >> 18;
            const int i = l & 262143;
            const float4* s;
            switch (which) {
                case 0: s = w0; break; case 1: s = w1; break; case 2: s = w2; break;
                case 3: s = w3; break; case 4: s = w4; break; default: s = w5; break;
            }
            float4 v = s[i];
            w6h[l] = make_uint2(packh(v.x, v.y),  packh(v.z, v.w));
            w6l[l] = make_uint2(packhl(v.x, v.y), packhl(v.z, v.w));
        } else {
            const int i = idx - R0N - R1N - R2N;
            float4 v = wout[i];
            wof[i] = make_uint2(packh(v.x, v.y), packh(v.z, v.w));
        }
    }
}

__global__ void transpose_wi(const float* __restrict__ w, __half* __restrict__ wt)
{
    __shared__ float tile[32][33];
    const int bx = blockIdx.x * 32, by = blockIdx.y * 32;
    const int tx = threadIdx.x & 31, ty = threadIdx.x >> 5;
#pragma unroll
    for (int dy = 0; dy < 32; dy += 8)
        tile[ty + dy][tx] = w[(size_t)(by + ty + dy) * 1024 + bx + tx];
    __syncthreads();
#pragma unroll
    for (int dy = 0; dy < 32; dy += 8)
        wt[(size_t)(bx + ty + dy) * 1024 + by + tx] = __float2half_rn(tile[tx][ty + dy]);
}

// ---------------------------------------------------------------------------
// cp.async pipelined fp16 GEMM (R13 dispatch form — known-good).
// C[M,N] = (Ah[+Al])[M,K] @ B[N,K]^T, K=1024, CTA 128x128, warp 64x64, BK=32,
// 4 stages, 2 CTAs/SM.
// TERMS: 2 = split A (hi+lo); 1 = single fp16 A.
// MODE:  0 = fp16 output Chh; 1 = projections (per-1024-col-seg epilogue);
//        2 = fp32 C.
// ---------------------------------------------------------------------------
#define STAGES 4
#define SECB   8192
#define STAGEB (3 * SECB)
#define GEMM_SMEM (STAGES * STAGEB)

template <int MODE, int TERMS>
__global__ void __launch_bounds__(128, 2)
gemm_f16(const __half* __restrict__ Ah, const __half* __restrict__ Al, int lda,
         const __half* __restrict__ B,
         const float* __restrict__ q0, const float* __restrict__ q1,
         const float* __restrict__ q2, const float* __restrict__ q3,
         const float* __restrict__ q4,
         float* __restrict__ C, int ldc,
         __half* __restrict__ Chh)
{
    extern __shared__ __align__(128) char smem[];
    const uint32_t sbase = (uint32_t)__cvta_generic_to_shared(smem);

    const int tid  = threadIdx.x;
    const int w    = tid >> 5;
    const int lane = tid & 31;
    const int wm   = w & 1;
    const int wn   = w >> 1;

    const int m0 = blockIdx.y * 128;
    const int n0 = blockIdx.x * 128;

    const __half* Ahp = Ah + (size_t)m0 * lda;
    const __half* Alp = (TERMS == 2) ? (Al + (size_t)m0 * lda) : nullptr;
    const __half* Bp  = B  + (size_t)n0 * KDIM;

    auto load_stage = [&](int buf, int k0) {
        const uint32_t db = sbase + (uint32_t)(buf * STAGEB);
        const int NCH = (TERMS == 2) ? 12 : 8;
#pragma unroll
        for (int i = 0; i < NCH; i++) {
            const int ci  = tid + i * 128;
            const int s2  = ci >> 9;
            const int r   = (ci >> 2) & 127;
            const int kq  = ci & 3;
            const __half* gp;
            uint32_t secoff;
            if (TERMS == 2) {
                if      (s2 == 0) { gp = Ahp + (size_t)r * lda; secoff = 0; }
                else if (s2 == 1) { gp = Alp + (size_t)r * lda; secoff = SECB; }
                else              { gp = Bp  + (size_t)r * KDIM; secoff = 2 * SECB; }
            } else {
                if (s2 == 0) { gp = Ahp + (size_t)r * lda; secoff = 0; }
                else         { gp = Bp  + (size_t)r * KDIM; secoff = 2 * SECB; }
            }
            gp += k0 + kq * 8;
            const uint32_t d = db + secoff + (uint32_t)(r * 64 + ((kq * 16) ^ ((r * 8) & 0x30)));
            cp16(d, gp);
        }
    };

    const int a_r  = (lane & 7) + ((lane >> 3) & 1) * 8;
    const int ak2  = ((lane >> 4) & 1) * 16;
    const uint32_t axr = (uint32_t)((a_r << 3) & 0x30);
    const int g    = lane >> 3;
    const int b_r  = ((g >> 1) * 8) + (lane & 7);
    const int bk2  = (g & 1) * 16;
    const uint32_t bxr = (uint32_t)((b_r << 3) & 0x30);

    uint32_t aoff[4], boff[4];
#pragma unroll
    for (int mi = 0; mi < 4; mi++) aoff[mi] = (uint32_t)((wm * 64 + mi * 16 + a_r) * 64);
#pragma unroll
    for (int gi = 0; gi < 4; gi++) boff[gi] = (uint32_t)(2 * SECB + (wn * 64 + gi * 16 + b_r) * 64);

    float acc[4][8][4] = {};

    load_stage(0, 0);
    asm volatile("cp.async.commit_group;\n");
    load_stage(1, 32);
    asm volatile("cp.async.commit_group;\n");
    load_stage(2, 64);
    asm volatile("cp.async.commit_group;\n");

    const int S = KDIM / 32;
    for (int s = 0; s < S; s++) {
        asm volatile("cp.async.wait_group 2;\n" ::: "memory");
        __syncthreads();
        if (s + 3 < S) load_stage((s + 3) & (STAGES - 1), (s + 3) * 32);
        asm volatile("cp.async.commit_group;\n");

        const uint32_t bb = sbase + (uint32_t)((s & (STAGES - 1)) * STAGEB);
#pragma unroll
        for (int kb = 0; kb < 2; kb++) {
            const uint32_t kx = (uint32_t)(kb * 32);
            uint32_t Bf[4][4];
#pragma unroll
            for (int gi = 0; gi < 4; gi++) {
                const uint32_t ba = bb + boff[gi] + ((kx + bk2) ^ bxr);
                LDSM_X4(Bf[gi][0], Bf[gi][1], Bf[gi][2], Bf[gi][3], ba);
            }
            {
                uint32_t Af[4][4];
#pragma unroll
                for (int mi = 0; mi < 4; mi++) {
                    const uint32_t aa = bb + aoff[mi] + ((kx + ak2) ^ axr);
                    LDSM_X4(Af[mi][0], Af[mi][1], Af[mi][2], Af[mi][3], aa);
                }
#pragma unroll
                for (int gi = 0; gi < 4; gi++)
#pragma unroll
                    for (int mi = 0; mi < 4; mi++)
#pragma unroll
                        for (int hf = 0; hf < 2; hf++)
                            MMA_F16(acc[mi][gi * 2 + hf], Af[mi], Bf[gi][2 * hf], Bf[gi][2 * hf + 1]);
            }
            if (TERMS == 2) {
                uint32_t Af[4][4];
#pragma unroll
                for (int mi = 0; mi < 4; mi++) {
                    const uint32_t aa = bb + aoff[mi] + ((kx + ak2) ^ axr) + SECB;
                    LDSM_X4(Af[mi][0], Af[mi][1], Af[mi][2], Af[mi][3], aa);
                }
#pragma unroll
                for (int gi = 0; gi < 4; gi++)
#pragma unroll
                    for (int mi = 0; mi < 4; mi++)
#pragma unroll
                        for (int hf = 0; hf < 2; hf++)
                            MMA_F16(acc[mi][gi * 2 + hf], Af[mi], Bf[gi][2 * hf], Bf[gi][2 * hf + 1]);
            }
        }
    }

    const int qr = lane >> 2;
    const int qc = (lane & 3) * 2;
    const int seg = blockIdx.x >> 3;

    if (MODE == 1 && seg < 2) {
        const float* wn_ = (seg == 0) ? q0 : q1;
#pragma unroll
        for (int mi = 0; mi < 4; mi++)
#pragma unroll
            for (int rh = 0; rh < 2; rh++) {
                float ss = 0.0f;
#pragma unroll
                for (int ti = 0; ti < 8; ti++) {
                    float a = acc[mi][ti][2 * rh], b2 = acc[mi][ti][2 * rh + 1];
                    ss += a * a + b2 * b2;
                }
                ss += __shfl_xor_sync(0xffffffffu, ss, 1);
                ss += __shfl_xor_sync(0xffffffffu, ss, 2);
                const float sc = rsqrtf(ss * (1.0f / 64.0f) + 1e-6f);
#pragma unroll
                for (int ti = 0; ti < 8; ti++) {
                    acc[mi][ti][2 * rh]     *= sc * wn_[ti * 8 + qc];
                    acc[mi][ti][2 * rh + 1] *= sc * wn_[ti * 8 + qc + 1];
                }
            }
    }

#pragma unroll
    for (int mi = 0; mi < 4; mi++) {
#pragma unroll
        for (int ti = 0; ti < 8; ti++) {
            const int col = n0 + wn * 64 + ti * 8 + qc;
            float b0 = 0.f, b1 = 0.f;
            if (MODE == 1 && seg >= 3 && seg <= 5) {
                const float* bp = (seg == 3) ? q2 : (seg == 4) ? q3 : q4;
                const int cs = col & 1023;
                b0 = bp[cs]; b1 = bp[cs + 1];
            }
#pragma unroll
            for (int rh = 0; rh < 2; rh++) {
                const int row = m0 + wm * 64 + mi * 16 + rh * 8 + qr;
                float x0 = acc[mi][ti][2 * rh + 0];
                float x1 = acc[mi][ti][2 * rh + 1];
                if (MODE == 1) {
                    if (seg == 3)                  { x0 = expf(x0 + b0); x1 = expf(x1 + b1); }
                    else if (seg == 4 || seg == 5) { x0 = 1.0f / (1.0f + expf(-(x0 + b0)));
                                                     x1 = 1.0f / (1.0f + expf(-(x1 + b1))); }
                }
                if (MODE == 0) {
                    *(uint32_t*)&Chh[(size_t)row * ldc + col] = packh(x0, x1);
                } else {
                    *(float2*)&C[(size_t)row * ldc + col] = make_float2(x0, x1);
                }
            }
        }
    }
}

// ---------------------------------------------------------------------------
// Scan pass A (unchanged)
// ---------------------------------------------------------------------------
__global__ void __launch_bounds__(128, 4)
chunk_fwdA(const float* __restrict__ pj,
           float* __restrict__ dC, float* __restrict__ dN, float* __restrict__ G,
           float* __restrict__ numI, float* __restrict__ qd, float* __restrict__ denI)
{
    __shared__ float stage[2][5][64];
    __shared__ float red[4][64];
    __shared__ float denp[2];

    const int tid = threadIdx.x;
    const int cid = blockIdx.x;
    const int j   = cid & (NCHUNK - 1);
    const int bh  = cid >> 6;
    const int b   = bh >> 4;
    const int h   = bh & 15;
    const size_t base6 = ((size_t)b * LL + (size_t)j * CHUNK) * NPJ + (size_t)h * 64;

    const float* srcs[5] = { pj + base6,        pj + base6 + 1024, pj + base6 + 2048,
                             pj + base6 + 3072, pj + base6 + 4096 };

    const int  arr = tid >> 4;
    const int  ch  = tid & 15;
    const bool loader = (tid < 80);
    const float* mySrc = srcs[loader ? arr : 0] + ch * 4;
    const uint32_t mydst0 = (uint32_t)__cvta_generic_to_shared(&stage[0][0][0]) + (arr * 64 + ch * 4) * 4;
    const uint32_t mydst1 = mydst0 + 5 * 64 * 4;

    if (loader) cp16(mydst0, mySrc);
    asm volatile("cp.async.commit_group;\n");

    const int r = tid >> 5;
    const int c = tid & 31;
    float C0[16], C1[16];
#pragma unroll
    for (int i = 0; i < 16; i++) { C0[i] = 0.0f; C1[i] = 0.0f; }
    float nreg = 0.0f, cum = 1.0f;

    float* numIp = numI + (size_t)cid * 4096;
    float* qdp   = qd   + (size_t)cid * 4096;
    float* denIp = denI + (size_t)cid * 64;

    for (int t = 0; t < CHUNK; t++) {
        asm volatile("cp.async.wait_group 0;\n" ::: "memory");
        __syncthreads();
        const int cur = t & 1;

        if (t + 1 < CHUNK && loader)
            cp16(cur ? mydst0 : mydst1, mySrc + (size_t)(t + 1) * NPJ);
        asm volatile("cp.async.commit_group;\n");

        const float* S   = &stage[cur][0][0];
        const float* qs  = S;
        const float* ks  = S + 64;
        const float* vs  = S + 128;
        const float* is_ = S + 192;
        const float* fs  = S + 256;

        float v0 = vs[c], v1 = vs[c + 32];
        float pn0 = 0.0f, pn1 = 0.0f;

#define ROWOP(ff, qq, aa, idx) { float _a = (aa);                              \
        C0[idx] = fmaf((ff), C0[idx], _a * v0); pn0 = fmaf((qq), C0[idx], pn0);\
        C1[idx] = fmaf((ff), C1[idx], _a * v1); pn1 = fmaf((qq), C1[idx], pn1); }

#pragma unroll
        for (int dd = 0; dd < 16; dd += 4) {
            int d = r * 16 + dd;
            float4 f4 = *(const float4*)&fs[d];
            float4 q4 = *(const float4*)&qs[d];
            float4 i4 = *(const float4*)&is_[d];
            float4 k4 = *(const float4*)&ks[d];
            ROWOP(f4.x, q4.x, i4.x * k4.x, dd + 0);
            ROWOP(f4.y, q4.y, i4.y * k4.y, dd + 1);
            ROWOP(f4.z, q4.z, i4.z * k4.z, dd + 2);
            ROWOP(f4.w, q4.w, i4.w * k4.w, dd + 3);
        }
#undef ROWOP

        red[r][c]      = pn0;
        red[r][c + 32] = pn1;

        float qdv = 0.0f;
        if (tid < 64) {
            float a = is_[tid] * ks[tid];
            nreg = fmaf(fs[tid], nreg, a);
            cum *= fs[tid];
            qdv = qs[tid] * cum;
            float dp = qs[tid] * nreg;
#pragma unroll
            for (int o = 16; o; o >>= 1) dp += __shfl_xor_sync(0xffffffffu, dp, o);
            if ((tid & 31) == 0) denp[tid >> 5] = dp;
        }
        __syncthreads();

        if (tid < 64) {
            float num = red[0][tid] + red[1][tid] + red[2][tid] + red[3][tid];
            numIp[t * 64 + tid] = num;
            qdp[t * 64 + tid]   = qdv;
            if (tid == 0) denIp[t] = denp[0] + denp[1];
        }
    }

    float* dCp = dC + (size_t)cid * 4096;
#pragma unroll
    for (int dd = 0; dd < 16; dd++) {
        dCp[(r * 16 + dd) * 64 + c]      = C0[dd];
        dCp[(r * 16 + dd) * 64 + c + 32] = C1[dd];
    }
    if (tid < 64) {
        dN[(size_t)cid * 64 + tid] = nreg;
        G [(size_t)cid * 64 + tid] = cum;
    }
}

// ---------------------------------------------------------------------------
// Parallel carry (unchanged)
// ---------------------------------------------------------------------------
__global__ void __launch_bounds__(128)
chunk_carryP(const float* __restrict__ dC, const float* __restrict__ dN,
             const float* __restrict__ G,
             float* __restrict__ Cst, float* __restrict__ Nst)
{
    const int bh  = blockIdx.x;
    const int y   = blockIdx.y;
    const int tid = threadIdx.x;

    if (y < 8) {
        const int el = y * 512 + tid * 4;
        const int d  = el >> 6;
        float4 Cv = make_float4(0.f, 0.f, 0.f, 0.f);
        for (int j = 0; j < NCHUNK; j++) {
            const size_t cid = (size_t)bh * NCHUNK + j;
            *(float4*)&Cst[cid * 4096 + el] = Cv;
            const float g = G[cid * 64 + d];
            float4 dv = *(const float4*)&dC[cid * 4096 + el];
            Cv.x = fmaf(g, Cv.x, dv.x);
            Cv.y = fmaf(g, Cv.y, dv.y);
            Cv.z = fmaf(g, Cv.z, dv.z);
            Cv.w = fmaf(g, Cv.w, dv.w);
        }
    } else if (tid < 16) {
        const int e = tid * 4;
        float4 nv = make_float4(0.f, 0.f, 0.f, 0.f);
        for (int j = 0; j < NCHUNK; j++) {
            const size_t cid = (size_t)bh * NCHUNK + j;
            *(float4*)&Nst[cid * 64 + e] = nv;
            float4 gv = *(const float4*)&G[cid * 64 + e];
            float4 dn = *(const float4*)&dN[cid * 64 + e];
            nv.x = fmaf(gv.x, nv.x, dn.x);
            nv.y = fmaf(gv.y, nv.y, dn.y);
            nv.z = fmaf(gv.z, nv.z, dn.z);
            nv.w = fmaf(gv.w, nv.w, dn.w);
        }
    }
}

// ---------------------------------------------------------------------------
// Scan pass B (unchanged)
// ---------------------------------------------------------------------------
__global__ void __launch_bounds__(128)
chunk_inter(const float* __restrict__ pj,
            const float* __restrict__ Cst, const float* __restrict__ Nst,
            const float* __restrict__ numI, const float* __restrict__ qd,
            const float* __restrict__ denI,
            __half* __restrict__ hh)
{
    __shared__ float qs_[64 * 65];
    __shared__ float cs_[64 * 64];
    __shared__ float ns_[64], den_[64], dI_[64];

    const int tid = threadIdx.x;
    const int cid = blockIdx.x;
    const int j   = cid & (NCHUNK - 1);
    const int bh  = cid >> 6;
    const int b   = bh >> 4;
    const int h   = bh & 15;
    const size_t row0 = (size_t)b * LL + (size_t)j * CHUNK;

#pragma unroll
    for (int i = 0; i < 8; i++) {
        const int lin = tid + i * 128;
        const int t   = lin >> 4;
        const int dg  = (lin & 15) * 4;
        float4 qv = *(const float4*)&qd [(size_t)cid * 4096 + t * 64 + dg];
        qs_[t * 65 + dg + 0] = qv.x; qs_[t * 65 + dg + 1] = qv.y;
        qs_[t * 65 + dg + 2] = qv.z; qs_[t * 65 + dg + 3] = qv.w;
        *(float4*)&cs_[t * 64 + dg] = *(const float4*)&Cst[(size_t)cid * 4096 + t * 64 + dg];
    }
    if (tid < 64) {
        ns_[tid] = Nst [(size_t)cid * 64 + tid];
        dI_[tid] = denI[(size_t)cid * 64 + tid];
    }
    __syncthreads();

    if (tid < 64) {
        float s = dI_[tid];
#pragma unroll 8
        for (int d = 0; d < 64; d++) s = fmaf(qs_[tid * 65 + d], ns_[d], s);
        den_[tid] = fmaxf(s, 1.0f);
    }
    __syncthreads();

    const int tg = tid >> 3;
    const int eg = tid & 7;
    const int t0 = tg * 4;
    const int e0 = eg * 8;

    float acc[4][8];
#pragma unroll
    for (int a = 0; a < 4; a++) {
        float4 u0 = *(const float4*)&numI[(size_t)cid * 4096 + (t0 + a) * 64 + e0];
        float4 u1 = *(const float4*)&numI[(size_t)cid * 4096 + (t0 + a) * 64 + e0 + 4];
        acc[a][0] = u0.x; acc[a][1] = u0.y; acc[a][2] = u0.z; acc[a][3] = u0.w;
        acc[a][4] = u1.x; acc[a][5] = u1.y; acc[a][6] = u1.z; acc[a][7] = u1.w;
    }

#pragma unroll 4
    for (int d = 0; d < 64; d++) {
        float q0 = qs_[(t0 + 0) * 65 + d];
        float q1 = qs_[(t0 + 1) * 65 + d];
        float q2 = qs_[(t0 + 2) * 65 + d];
        float q3 = qs_[(t0 + 3) * 65 + d];
        float4 c0 = *(const float4*)&cs_[d * 64 + e0];
        float4 c1 = *(const float4*)&cs_[d * 64 + e0 + 4];
        float cv[8] = { c0.x, c0.y, c0.z, c0.w, c1.x, c1.y, c1.z, c1.w };
#pragma unroll
        for (int bb2 = 0; bb2 < 8; bb2++) {
            acc[0][bb2] = fmaf(q0, cv[bb2], acc[0][bb2]);
            acc[1][bb2] = fmaf(q1, cv[bb2], acc[1][bb2]);
            acc[2][bb2] = fmaf(q2, cv[bb2], acc[2][bb2]);
            acc[3][bb2] = fmaf(q3, cv[bb2], acc[3][bb2]);
        }
    }

#pragma unroll
    for (int a = 0; a < 4; a++) {
        const size_t grow = row0 + t0 + a;
        const size_t pb = grow * NPJ + (size_t)h * 64 + e0;
        float4 og0 = *(const float4*)&pj[pb + 5120];
        float4 og1 = *(const float4*)&pj[pb + 5124];
        float4 gt0 = *(const float4*)&pj[pb + 6144];
        float4 gt1 = *(const float4*)&pj[pb + 6148];
        float ogv[8] = { og0.x, og0.y, og0.z, og0.w, og1.x, og1.y, og1.z, og1.w };
        float gtv[8] = { gt0.x, gt0.y, gt0.z, gt0.w, gt1.x, gt1.y, gt1.z, gt1.w };
        const float dinv = 1.0f / den_[t0 + a];
        uint32_t packed[4];
#pragma unroll
        for (int p = 0; p < 4; p++) {
            float o0 = (acc[a][2*p]   * dinv) * ogv[2*p]   * (1.0f / (1.0f + expf(-gtv[2*p])));
            float o1 = (acc[a][2*p+1] * dinv) * ogv[2*p+1] * (1.0f / (1.0f + expf(-gtv[2*p+1])));
            packed[p] = packh(o0, o1);
        }
        *(uint4*)&hh[grow * 1024 + (size_t)h * 64 + e0] =
            make_uint4(packed[0], packed[1], packed[2], packed[3]);
    }
}

// ---------------------------------------------------------------------------
// Launch
// ---------------------------------------------------------------------------
extern "C" void kernel_launch(void* const* d_in, const int* in_sizes, int n_in,
                              void* d_out, int out_size)
{
    const float* x     = (const float*)d_in[0];
    const float* w_in  = (const float*)d_in[1];
    const float* w_q   = (const float*)d_in[2];
    const float* w_k   = (const float*)d_in[3];
    const float* w_v   = (const float*)d_in[4];
    const float* w_i   = (const float*)d_in[5];
    const float* b_i   = (const float*)d_in[6];
    const float* w_f   = (const float*)d_in[7];
    const float* b_f   = (const float*)d_in[8];
    const float* w_o   = (const float*)d_in[9];
    const float* b_o   = (const float*)d_in[10];
    const float* w_qn  = (const float*)d_in[11];
    const float* w_kn  = (const float*)d_in[12];
    const float* w_out = (const float*)d_in[13];
    float* out = (float*)d_out;

    float *pj, *dC, *dN, *G, *Cst, *Nst, *numI, *qdb, *denI;
    __half *xh, *hh, *wiT, *w6h, *w6l, *wff, *wof;
    cudaGetSymbolAddress((void**)&pj,   g_pj);
    cudaGetSymbolAddress((void**)&dC,   g_dC);
    cudaGetSymbolAddress((void**)&dN,   g_dN);
    cudaGetSymbolAddress((void**)&G,    g_G);
    cudaGetSymbolAddress((void**)&Cst,  g_Cst);
    cudaGetSymbolAddress((void**)&Nst,  g_Nst);
    cudaGetSymbolAddress((void**)&numI, g_numI);
    cudaGetSymbolAddress((void**)&qdb,  g_qd);
    cudaGetSymbolAddress((void**)&denI, g_denI);
    cudaGetSymbolAddress((void**)&xh,   g_xh);
    cudaGetSymbolAddress((void**)&hh,   g_hh);
    cudaGetSymbolAddress((void**)&wiT,  g_wiT);
    cudaGetSymbolAddress((void**)&w6h,  g_w6h);
    cudaGetSymbolAddress((void**)&w6l,  g_w6l);
    cudaGetSymbolAddress((void**)&wff,  g_wff);
    cudaGetSymbolAddress((void**)&wof,  g_wof);

    cudaFuncSetAttribute(gemm_f16<0,2>, cudaFuncAttributeMaxDynamicSharedMemorySize, GEMM_SMEM);
    cudaFuncSetAttribute(gemm_f16<1,1>, cudaFuncAttributeMaxDynamicSharedMemorySize, GEMM_SMEM);
    cudaFuncSetAttribute(gemm_f16<2,1>, cudaFuncAttributeMaxDynamicSharedMemorySize, GEMM_SMEM);

    // ---- pass 0: conversions (fused) ----
    transpose_wi<<<dim3(32, 32), 256>>>(w_in, wiT);
    cvt_all<<<1024, 256>>>((const float4*)x,
                           (const float4*)(w_in + (size_t)1024 * 1024),
                           (const float4*)w_q, (const float4*)w_k, (const float4*)w_v,
                           (const float4*)w_i, (const float4*)w_f, (const float4*)w_o,
                           (const float4*)w_out,
                           (uint2*)xh, (uint2*)(wff + (size_t)6144 * 1024),
                           (uint2*)w6h, (uint2*)w6l, (uint2*)wof);

    dim3 blk(128);

    // ---- Wfused[0:6144] = Wproj @ Wi_inner ----
    gemm_f16<0,2><<<dim3(1024 / 128, 6144 / 128), blk, GEMM_SMEM>>>(
        w6h, w6l, 1024, wiT, nullptr, nullptr, nullptr, nullptr, nullptr,
        nullptr, 1024, wff);

    // ---- merged projections + gate from x: pj[8192,7168] ----
    gemm_f16<1,1><<<dim3(NPJ / 128, MROWS / 128), blk, GEMM_SMEM>>>(
        xh, nullptr, 1024, wff, w_qn, w_kn, b_i, b_f, b_o,
        pj, NPJ, nullptr);

    // ---- chunk-parallel scan ----
    chunk_fwdA  <<<NCID, 128>>>(pj, dC, dN, G, numI, qdb, denI);
    chunk_carryP<<<dim3(BB * NH, 9), 128>>>(dC, dN, G, Cst, Nst);
    chunk_inter <<<NCID, 128>>>(pj, Cst, Nst, numI, qdb, denI, hh);

    // ---- output projection (single-term fp16 A) ----
    gemm_f16<2,1><<<dim3(1024 / 128, MROWS / 128), blk, GEMM_SMEM>>>(
        hh, nullptr, 1024, wof, nullptr, nullptr, nullptr, nullptr, nullptr,
        out, 1024, nullptr);
}

// round 17
// speedup vs baseline: 1.0848x; 1.0193x over previous
#include <cuda_runtime.h>
#include <cuda_fp16.h>
#include <math.h>
#include <stdint.h>

// Problem constants
#define BB   2
#define LL   4096
#define DIMD 1024
#define NH   16
#define HD   64
#define MROWS (BB * LL)          // 8192
#define KDIM 1024
#define CHUNK  64
#define NCHUNK (LL / CHUNK)      // 64
#define NCID   (BB * NH * NCHUNK) // 2048
#define NPJ  7168                // fused projection width: q|k|v|i|f|o|gate
#define PGRID 296

// ---------------------------------------------------------------------------
// Scratch
// ---------------------------------------------------------------------------
__device__ float g_pj[(size_t)MROWS * NPJ];
__device__ __half g_xh  [(size_t)MROWS * 1024];
__device__ __half g_hh  [(size_t)MROWS * 1024];
__device__ __half g_wiT [(size_t)1024 * 1024];
__device__ __half g_w6h [(size_t)6 * 1024 * 1024];
__device__ __half g_w6l [(size_t)6 * 1024 * 1024];
__device__ __half g_wff [(size_t)NPJ * 1024];
__device__ __half g_wof [(size_t)1024 * 1024];
__device__ float g_dC  [(size_t)NCID * 4096];
__device__ float g_dN  [(size_t)NCID * 64];
__device__ float g_G   [(size_t)NCID * 64];
__device__ float g_Cst [(size_t)NCID * 4096];
__device__ float g_Nst [(size_t)NCID * 64];
__device__ float g_numI[(size_t)NCID * 4096];
__device__ float g_qd  [(size_t)NCID * 4096];
__device__ float g_denI[(size_t)NCID * 64];
__device__ int   g_ctr [4];       // work-stealing counters (reset by cvt_all)

// ---------------------------------------------------------------------------
// helpers
// ---------------------------------------------------------------------------
__device__ __forceinline__ uint32_t packh(float x, float y) {
    __half hx = __float2half_rn(x);
    __half hy = __float2half_rn(y);
    return (uint32_t)__half_as_ushort(hx) | ((uint32_t)__half_as_ushort(hy) << 16);
}
__device__ __forceinline__ uint32_t packhl(float x, float y) {
    __half hx = __float2half_rn(x);
    __half hy = __float2half_rn(y);
    return packh(x - __half2float(hx), y - __half2float(hy));
}
__device__ __forceinline__ void cp16(uint32_t s, const void* g)
{
    asm volatile("cp.async.ca.shared.global [%0], [%1], 16;\n" :: "r"(s), "l"(g));
}

#define LDSM_X4(r0, r1, r2, r3, addr) \
    asm volatile("ldmatrix.sync.aligned.m8n8.x4.shared.b16 {%0,%1,%2,%3}, [%4];" \
                 : "=r"(r0), "=r"(r1), "=r"(r2), "=r"(r3) : "r"(addr))

#define MMA_F16(d, a, b0, b1) \
    asm volatile("mma.sync.aligned.m16n8k16.row.col.f32.f16.f16.f32 " \
                 "{%0,%1,%2,%3}, {%4,%5,%6,%7}, {%8,%9}, {%0,%1,%2,%3};" \
                 : "+f"((d)[0]), "+f"((d)[1]), "+f"((d)[2]), "+f"((d)[3]) \
                 : "r"((a)[0]), "r"((a)[1]), "r"((a)[2]), "r"((a)[3]), \
                   "r"(b0), "r"(b1))

// ---------------------------------------------------------------------------
// Pass 0: fused conversion mega-kernel (+ counter reset for GEMM work-stealing)
// ---------------------------------------------------------------------------
#define R0N 2097152
#define R1N 262144
#define R2N 1572864
#define R3N 262144
#define RTOT (R0N + R1N + R2N + R3N)

__global__ void cvt_all(const float4* __restrict__ x,
                        const float4* __restrict__ wgate,
                        const float4* __restrict__ w0, const float4* __restrict__ w1,
                        const float4* __restrict__ w2, const float4* __restrict__ w3,
                        const float4* __restrict__ w4, const float4* __restrict__ w5,
                        const float4* __restrict__ wout,
                        uint2* __restrict__ xh, uint2* __restrict__ wffgate,
                        uint2* __restrict__ w6h, uint2* __restrict__ w6l,
                        uint2* __restrict__ wof)
{
    if (blockIdx.x == 0 && threadIdx.x < 4) g_ctr[threadIdx.x] = PGRID;

    for (int idx = blockIdx.x * 256 + threadIdx.x; idx < RTOT; idx += gridDim.x * 256) {
        if (idx < R0N) {
            float4 v = x[idx];
            xh[idx] = make_uint2(packh(v.x, v.y), packh(v.z, v.w));
        } else if (idx < R0N + R1N) {
            const int i = idx - R0N;
            float4 v = wgate[i];
            wffgate[i] = make_uint2(packh(v.x, v.y), packh(v.z, v.w));
        } else if (idx < R0N + R1N + R2N) {
            const int l = idx - R0N - R1N;
            const int which = l >> 18;
            const int i = l & 262143;
            const float4* s;
            switch (which) {
                case 0: s = w0; break; case 1: s = w1; break; case 2: s = w2; break;
                case 3: s = w3; break; case 4: s = w4; break; default: s = w5; break;
            }
            float4 v = s[i];
            w6h[l] = make_uint2(packh(v.x, v.y),  packh(v.z, v.w));
            w6l[l] = make_uint2(packhl(v.x, v.y), packhl(v.z, v.w));
        } else {
            const int i = idx - R0N - R1N - R2N;
            float4 v = wout[i];
            wof[i] = make_uint2(packh(v.x, v.y), packh(v.z, v.w));
        }
    }
}

__global__ void transpose_wi(const float* __restrict__ w, __half* __restrict__ wt)
{
    __shared__ float tile[32][33];
    const int bx = blockIdx.x * 32, by = blockIdx.y * 32;
    const int tx = threadIdx.x & 31, ty = threadIdx.x >> 5;
#pragma unroll
    for (int dy = 0; dy < 32; dy += 8)
        tile[ty + dy][tx] = w[(size_t)(by + ty + dy) * 1024 + bx + tx];
    __syncthreads();
#pragma unroll
    for (int dy = 0; dy < 32; dy += 8)
        wt[(size_t)(bx + ty + dy) * 1024 + by + tx] = __float2half_rn(tile[tx][ty + dy]);
}

// ---------------------------------------------------------------------------
// Work-stealing persistent fp16 GEMM. Per-tile body is the R16 pipeline
// verbatim (prologue -> 32 steps -> epilogue); next tile comes from an atomic
// counter. MT/NT are template constants (div-by-const -> mul/shift).
// TERMS: 2 = split A (hi+lo); 1 = single fp16 A.
// MODE:  0 = fp16 output Chh; 1 = projections (per-1024-col-seg epilogue);
//        2 = fp32 C.
// ---------------------------------------------------------------------------
#define STAGES 4
#define SECB   8192
#define STAGEB (3 * SECB)
#define TILE_SLOT (STAGES * STAGEB)         // 98304
#define GEMM_SMEM (TILE_SLOT + 16)          // 98320

template <int MODE, int TERMS, int MT, int NT, int CID>
__global__ void __launch_bounds__(128, 2)
gemm_f16(const __half* __restrict__ Ah, const __half* __restrict__ Al, int lda,
         const __half* __restrict__ B,
         const float* __restrict__ q0, const float* __restrict__ q1,
         const float* __restrict__ q2, const float* __restrict__ q3,
         const float* __restrict__ q4,
         float* __restrict__ C, int ldc,
         __half* __restrict__ Chh)
{
    extern __shared__ __align__(128) char smem[];
    const uint32_t sbase = (uint32_t)__cvta_generic_to_shared(smem);
    int* shtile = (int*)(smem + TILE_SLOT);

    const int tid  = threadIdx.x;
    const int w    = tid >> 5;
    const int lane = tid & 31;
    const int wm   = w & 1;
    const int wn   = w >> 1;

    auto load_stage = [&](const __half* Ahp, const __half* Alp, const __half* Bp,
                          int buf, int k0) {
        const uint32_t db = sbase + (uint32_t)(buf * STAGEB);
        const int NCH = (TERMS == 2) ? 12 : 8;
#pragma unroll
        for (int i = 0; i < NCH; i++) {
            const int ci  = tid + i * 128;
            const int s2  = ci >> 9;
            const int r   = (ci >> 2) & 127;
            const int kq  = ci & 3;
            const __half* gp;
            uint32_t secoff;
            if (TERMS == 2) {
                if      (s2 == 0) { gp = Ahp + (size_t)r * lda; secoff = 0; }
                else if (s2 == 1) { gp = Alp + (size_t)r * lda; secoff = SECB; }
                else              { gp = Bp  + (size_t)r * KDIM; secoff = 2 * SECB; }
            } else {
                if (s2 == 0) { gp = Ahp + (size_t)r * lda; secoff = 0; }
                else         { gp = Bp  + (size_t)r * KDIM; secoff = 2 * SECB; }
            }
            gp += k0 + kq * 8;
            const uint32_t d = db + secoff + (uint32_t)(r * 64 + ((kq * 16) ^ ((r * 8) & 0x30)));
            cp16(d, gp);
        }
    };

    const int a_r  = (lane & 7) + ((lane >> 3) & 1) * 8;
    const int ak2  = ((lane >> 4) & 1) * 16;
    const uint32_t axr = (uint32_t)((a_r << 3) & 0x30);
    const int g    = lane >> 3;
    const int b_r  = ((g >> 1) * 8) + (lane & 7);
    const int bk2  = (g & 1) * 16;
    const uint32_t bxr = (uint32_t)((b_r << 3) & 0x30);

    uint32_t aoff[4], boff[4];
#pragma unroll
    for (int mi = 0; mi < 4; mi++) aoff[mi] = (uint32_t)((wm * 64 + mi * 16 + a_r) * 64);
#pragma unroll
    for (int gi = 0; gi < 4; gi++) boff[gi] = (uint32_t)(2 * SECB + (wn * 64 + gi * 16 + b_r) * 64);

    const int qr = lane >> 2;
    const int qc = (lane & 3) * 2;

    int tile = (int)blockIdx.x;

    while (tile < MT * NT) {
        const int mtl = tile / NT;            // compile-time NT -> mul/shift
        const int ntl = tile - mtl * NT;
        const int m0  = mtl * 128;
        const int n0  = ntl * 128;

        const __half* Ahp = Ah + (size_t)m0 * lda;
        const __half* Alp = (TERMS == 2) ? (Al + (size_t)m0 * lda) : nullptr;
        const __half* Bp  = B  + (size_t)n0 * KDIM;

        float acc[4][8][4] = {};

        load_stage(Ahp, Alp, Bp, 0, 0);
        asm volatile("cp.async.commit_group;\n");
        load_stage(Ahp, Alp, Bp, 1, 32);
        asm volatile("cp.async.commit_group;\n");
        load_stage(Ahp, Alp, Bp, 2, 64);
        asm volatile("cp.async.commit_group;\n");

        const int S = KDIM / 32;
        for (int s = 0; s < S; s++) {
            asm volatile("cp.async.wait_group 2;\n" ::: "memory");
            __syncthreads();
            if (s + 3 < S) load_stage(Ahp, Alp, Bp, (s + 3) & (STAGES - 1), (s + 3) * 32);
            asm volatile("cp.async.commit_group;\n");

            const uint32_t bb = sbase + (uint32_t)((s & (STAGES - 1)) * STAGEB);
#pragma unroll
            for (int kb = 0; kb < 2; kb++) {
                const uint32_t kx = (uint32_t)(kb * 32);
                uint32_t Bf[4][4];
#pragma unroll
                for (int gi = 0; gi < 4; gi++) {
                    const uint32_t ba = bb + boff[gi] + ((kx + bk2) ^ bxr);
                    LDSM_X4(Bf[gi][0], Bf[gi][1], Bf[gi][2], Bf[gi][3], ba);
                }
                {
                    uint32_t Af[4][4];
#pragma unroll
                    for (int mi = 0; mi < 4; mi++) {
                        const uint32_t aa = bb + aoff[mi] + ((kx + ak2) ^ axr);
                        LDSM_X4(Af[mi][0], Af[mi][1], Af[mi][2], Af[mi][3], aa);
                    }
#pragma unroll
                    for (int gi = 0; gi < 4; gi++)
#pragma unroll
                        for (int mi = 0; mi < 4; mi++)
#pragma unroll
                            for (int hf = 0; hf < 2; hf++)
                                MMA_F16(acc[mi][gi * 2 + hf], Af[mi], Bf[gi][2 * hf], Bf[gi][2 * hf + 1]);
                }
                if (TERMS == 2) {
                    uint32_t Af[4][4];
#pragma unroll
                    for (int mi = 0; mi < 4; mi++) {
                        const uint32_t aa = bb + aoff[mi] + ((kx + ak2) ^ axr) + SECB;
                        LDSM_X4(Af[mi][0], Af[mi][1], Af[mi][2], Af[mi][3], aa);
                    }
#pragma unroll
                    for (int gi = 0; gi < 4; gi++)
#pragma unroll
                        for (int mi = 0; mi < 4; mi++)
#pragma unroll
                            for (int hf = 0; hf < 2; hf++)
                                MMA_F16(acc[mi][gi * 2 + hf], Af[mi], Bf[gi][2 * hf], Bf[gi][2 * hf + 1]);
                }
            }
        }

        const int seg = ntl >> 3;

        if (MODE == 1 && seg < 2) {
            const float* wn_ = (seg == 0) ? q0 : q1;
#pragma unroll
            for (int mi = 0; mi < 4; mi++)
#pragma unroll
                for (int rh = 0; rh < 2; rh++) {
                    float ss = 0.0f;
#pragma unroll
                    for (int ti = 0; ti < 8; ti++) {
                        float a = acc[mi][ti][2 * rh], b2 = acc[mi][ti][2 * rh + 1];
                        ss += a * a + b2 * b2;
                    }
                    ss += __shfl_xor_sync(0xffffffffu, ss, 1);
                    ss += __shfl_xor_sync(0xffffffffu, ss, 2);
                    const float sc = rsqrtf(ss * (1.0f / 64.0f) + 1e-6f);
#pragma unroll
                    for (int ti = 0; ti < 8; ti++) {
                        acc[mi][ti][2 * rh]     *= sc * wn_[ti * 8 + qc];
                        acc[mi][ti][2 * rh + 1] *= sc * wn_[ti * 8 + qc + 1];
                    }
                }
        }

#pragma unroll
        for (int mi = 0; mi < 4; mi++) {
#pragma unroll
            for (int ti = 0; ti < 8; ti++) {
                const int col = n0 + wn * 64 + ti * 8 + qc;
                float b0 = 0.f, b1 = 0.f;
                if (MODE == 1 && seg >= 3 && seg <= 5) {
                    const float* bp = (seg == 3) ? q2 : (seg == 4) ? q3 : q4;
                    const int cs = col & 1023;
                    b0 = bp[cs]; b1 = bp[cs + 1];
                }
#pragma unroll
                for (int rh = 0; rh < 2; rh++) {
                    const int row = m0 + wm * 64 + mi * 16 + rh * 8 + qr;
                    float x0 = acc[mi][ti][2 * rh + 0];
                    float x1 = acc[mi][ti][2 * rh + 1];
                    if (MODE == 1) {
                        if (seg == 3)                  { x0 = expf(x0 + b0); x1 = expf(x1 + b1); }
                        else if (seg == 4 || seg == 5) { x0 = 1.0f / (1.0f + expf(-(x0 + b0)));
                                                         x1 = 1.0f / (1.0f + expf(-(x1 + b1))); }
                    }
                    if (MODE == 0) {
                        *(uint32_t*)&Chh[(size_t)row * ldc + col] = packh(x0, x1);
                    } else {
                        *(float2*)&C[(size_t)row * ldc + col] = make_float2(x0, x1);
                    }
                }
            }
        }

        // fetch next tile (work stealing)
        __syncthreads();
        if (tid == 0) *shtile = atomicAdd(&g_ctr[CID], 1);
        __syncthreads();
        tile = *shtile;
    }
}

// ---------------------------------------------------------------------------
// Scan pass A (unchanged)
// ---------------------------------------------------------------------------
__global__ void __launch_bounds__(128, 4)
chunk_fwdA(const float* __restrict__ pj,
           float* __restrict__ dC, float* __restrict__ dN, float* __restrict__ G,
           float* __restrict__ numI, float* __restrict__ qd, float* __restrict__ denI)
{
    __shared__ float stage[2][5][64];
    __shared__ float red[4][64];
    __shared__ float denp[2];

    const int tid = threadIdx.x;
    const int cid = blockIdx.x;
    const int j   = cid & (NCHUNK - 1);
    const int bh  = cid >> 6;
    const int b   = bh >> 4;
    const int h   = bh & 15;
    const size_t base6 = ((size_t)b * LL + (size_t)j * CHUNK) * NPJ + (size_t)h * 64;

    const float* srcs[5] = { pj + base6,        pj + base6 + 1024, pj + base6 + 2048,
                             pj + base6 + 3072, pj + base6 + 4096 };

    const int  arr = tid >> 4;
    const int  ch  = tid & 15;
    const bool loader = (tid < 80);
    const float* mySrc = srcs[loader ? arr : 0] + ch * 4;
    const uint32_t mydst0 = (uint32_t)__cvta_generic_to_shared(&stage[0][0][0]) + (arr * 64 + ch * 4) * 4;
    const uint32_t mydst1 = mydst0 + 5 * 64 * 4;

    if (loader) cp16(mydst0, mySrc);
    asm volatile("cp.async.commit_group;\n");

    const int r = tid >> 5;
    const int c = tid & 31;
    float C0[16], C1[16];
#pragma unroll
    for (int i = 0; i < 16; i++) { C0[i] = 0.0f; C1[i] = 0.0f; }
    float nreg = 0.0f, cum = 1.0f;

    float* numIp = numI + (size_t)cid * 4096;
    float* qdp   = qd   + (size_t)cid * 4096;
    float* denIp = denI + (size_t)cid * 64;

    for (int t = 0; t < CHUNK; t++) {
        asm volatile("cp.async.wait_group 0;\n" ::: "memory");
        __syncthreads();
        const int cur = t & 1;

        if (t + 1 < CHUNK && loader)
            cp16(cur ? mydst0 : mydst1, mySrc + (size_t)(t + 1) * NPJ);
        asm volatile("cp.async.commit_group;\n");

        const float* S   = &stage[cur][0][0];
        const float* qs  = S;
        const float* ks  = S + 64;
        const float* vs  = S + 128;
        const float* is_ = S + 192;
        const float* fs  = S + 256;

        float v0 = vs[c], v1 = vs[c + 32];
        float pn0 = 0.0f, pn1 = 0.0f;

#define ROWOP(ff, qq, aa, idx) { float _a = (aa);                              \
        C0[idx] = fmaf((ff), C0[idx], _a * v0); pn0 = fmaf((qq), C0[idx], pn0);\
        C1[idx] = fmaf((ff), C1[idx], _a * v1); pn1 = fmaf((qq), C1[idx], pn1); }

#pragma unroll
        for (int dd = 0; dd < 16; dd += 4) {
            int d = r * 16 + dd;
            float4 f4 = *(const float4*)&fs[d];
            float4 q4 = *(const float4*)&qs[d];
            float4 i4 = *(const float4*)&is_[d];
            float4 k4 = *(const float4*)&ks[d];
            ROWOP(f4.x, q4.x, i4.x * k4.x, dd + 0);
            ROWOP(f4.y, q4.y, i4.y * k4.y, dd + 1);
            ROWOP(f4.z, q4.z, i4.z * k4.z, dd + 2);
            ROWOP(f4.w, q4.w, i4.w * k4.w, dd + 3);
        }
#undef ROWOP

        red[r][c]      = pn0;
        red[r][c + 32] = pn1;

        float qdv = 0.0f;
        if (tid < 64) {
            float a = is_[tid] * ks[tid];
            nreg = fmaf(fs[tid], nreg, a);
            cum *= fs[tid];
            qdv = qs[tid] * cum;
            float dp = qs[tid] * nreg;
#pragma unroll
            for (int o = 16; o; o >>= 1) dp += __shfl_xor_sync(0xffffffffu, dp, o);
            if ((tid & 31) == 0) denp[tid >> 5] = dp;
        }
        __syncthreads();

        if (tid < 64) {
            float num = red[0][tid] + red[1][tid] + red[2][tid] + red[3][tid];
            numIp[t * 64 + tid] = num;
            qdp[t * 64 + tid]   = qdv;
            if (tid == 0) denIp[t] = denp[0] + denp[1];
        }
    }

    float* dCp = dC + (size_t)cid * 4096;
#pragma unroll
    for (int dd = 0; dd < 16; dd++) {
        dCp[(r * 16 + dd) * 64 + c]      = C0[dd];
        dCp[(r * 16 + dd) * 64 + c + 32] = C1[dd];
    }
    if (tid < 64) {
        dN[(size_t)cid * 64 + tid] = nreg;
        G [(size_t)cid * 64 + tid] = cum;
    }
}

// ---------------------------------------------------------------------------
// Parallel carry (unchanged)
// ---------------------------------------------------------------------------
__global__ void __launch_bounds__(128)
chunk_carryP(const float* __restrict__ dC, const float* __restrict__ dN,
             const float* __restrict__ G,
             float* __restrict__ Cst, float* __restrict__ Nst)
{
    const int bh  = blockIdx.x;
    const int y   = blockIdx.y;
    const int tid = threadIdx.x;

    if (y < 8) {
        const int el = y * 512 + tid * 4;
        const int d  = el >> 6;
        float4 Cv = make_float4(0.f, 0.f, 0.f, 0.f);
        for (int j = 0; j < NCHUNK; j++) {
            const size_t cid = (size_t)bh * NCHUNK + j;
            *(float4*)&Cst[cid * 4096 + el] = Cv;
            const float g = G[cid * 64 + d];
            float4 dv = *(const float4*)&dC[cid * 4096 + el];
            Cv.x = fmaf(g, Cv.x, dv.x);
            Cv.y = fmaf(g, Cv.y, dv.y);
            Cv.z = fmaf(g, Cv.z, dv.z);
            Cv.w = fmaf(g, Cv.w, dv.w);
        }
    } else if (tid < 16) {
        const int e = tid * 4;
        float4 nv = make_float4(0.f, 0.f, 0.f, 0.f);
        for (int j = 0; j < NCHUNK; j++) {
            const size_t cid = (size_t)bh * NCHUNK + j;
            *(float4*)&Nst[cid * 64 + e] = nv;
            float4 gv = *(const float4*)&G[cid * 64 + e];
            float4 dn = *(const float4*)&dN[cid * 64 + e];
            nv.x = fmaf(gv.x, nv.x, dn.x);
            nv.y = fmaf(gv.y, nv.y, dn.y);
            nv.z = fmaf(gv.z, nv.z, dn.z);
            nv.w = fmaf(gv.w, nv.w, dn.w);
        }
    }
}

// ---------------------------------------------------------------------------
// Scan pass B (unchanged)
// ---------------------------------------------------------------------------
__global__ void __launch_bounds__(128)
chunk_inter(const float* __restrict__ pj,
            const float* __restrict__ Cst, const float* __restrict__ Nst,
            const float* __restrict__ numI, const float* __restrict__ qd,
            const float* __restrict__ denI,
            __half* __restrict__ hh)
{
    __shared__ float qs_[64 * 65];
    __shared__ float cs_[64 * 64];
    __shared__ float ns_[64], den_[64], dI_[64];

    const int tid = threadIdx.x;
    const int cid = blockIdx.x;
    const int j   = cid & (NCHUNK - 1);
    const int bh  = cid >> 6;
    const int b   = bh >> 4;
    const int h   = bh & 15;
    const size_t row0 = (size_t)b * LL + (size_t)j * CHUNK;

#pragma unroll
    for (int i = 0; i < 8; i++) {
        const int lin = tid + i * 128;
        const int t   = lin >> 4;
        const int dg  = (lin & 15) * 4;
        float4 qv = *(const float4*)&qd [(size_t)cid * 4096 + t * 64 + dg];
        qs_[t * 65 + dg + 0] = qv.x; qs_[t * 65 + dg + 1] = qv.y;
        qs_[t * 65 + dg + 2] = qv.z; qs_[t * 65 + dg + 3] = qv.w;
        *(float4*)&cs_[t * 64 + dg] = *(const float4*)&Cst[(size_t)cid * 4096 + t * 64 + dg];
    }
    if (tid < 64) {
        ns_[tid] = Nst [(size_t)cid * 64 + tid];
        dI_[tid] = denI[(size_t)cid * 64 + tid];
    }
    __syncthreads();

    if (tid < 64) {
        float s = dI_[tid];
#pragma unroll 8
        for (int d = 0; d < 64; d++) s = fmaf(qs_[tid * 65 + d], ns_[d], s);
        den_[tid] = fmaxf(s, 1.0f);
    }
    __syncthreads();

    const int tg = tid >> 3;
    const int eg = tid & 7;
    const int t0 = tg * 4;
    const int e0 = eg * 8;

    float acc[4][8];
#pragma unroll
    for (int a = 0; a < 4; a++) {
        float4 u0 = *(const float4*)&numI[(size_t)cid * 4096 + (t0 + a) * 64 + e0];
        float4 u1 = *(const float4*)&numI[(size_t)cid * 4096 + (t0 + a) * 64 + e0 + 4];
        acc[a][0] = u0.x; acc[a][1] = u0.y; acc[a][2] = u0.z; acc[a][3] = u0.w;
        acc[a][4] = u1.x; acc[a][5] = u1.y; acc[a][6] = u1.z; acc[a][7] = u1.w;
    }

#pragma unroll 4
    for (int d = 0; d < 64; d++) {
        float q0 = qs_[(t0 + 0) * 65 + d];
        float q1 = qs_[(t0 + 1) * 65 + d];
        float q2 = qs_[(t0 + 2) * 65 + d];
        float q3 = qs_[(t0 + 3) * 65 + d];
        float4 c0 = *(const float4*)&cs_[d * 64 + e0];
        float4 c1 = *(const float4*)&cs_[d * 64 + e0 + 4];
        float cv[8] = { c0.x, c0.y, c0.z, c0.w, c1.x, c1.y, c1.z, c1.w };
#pragma unroll
        for (int bb2 = 0; bb2 < 8; bb2++) {
            acc[0][bb2] = fmaf(q0, cv[bb2], acc[0][bb2]);
            acc[1][bb2] = fmaf(q1, cv[bb2], acc[1][bb2]);
            acc[2][bb2] = fmaf(q2, cv[bb2], acc[2][bb2]);
            acc[3][bb2] = fmaf(q3, cv[bb2], acc[3][bb2]);
        }
    }

#pragma unroll
    for (int a = 0; a < 4; a++) {
        const size_t grow = row0 + t0 + a;
        const size_t pb = grow * NPJ + (size_t)h * 64 + e0;
        float4 og0 = *(const float4*)&pj[pb + 5120];
        float4 og1 = *(const float4*)&pj[pb + 5124];
        float4 gt0 = *(const float4*)&pj[pb + 6144];
        float4 gt1 = *(const float4*)&pj[pb + 6148];
        float ogv[8] = { og0.x, og0.y, og0.z, og0.w, og1.x, og1.y, og1.z, og1.w };
        float gtv[8] = { gt0.x, gt0.y, gt0.z, gt0.w, gt1.x, gt1.y, gt1.z, gt1.w };
        const float dinv = 1.0f / den_[t0 + a];
        uint32_t packed[4];
#pragma unroll
        for (int p = 0; p < 4; p++) {
            float o0 = (acc[a][2*p]   * dinv) * ogv[2*p]   * (1.0f / (1.0f + expf(-gtv[2*p])));
            float o1 = (acc[a][2*p+1] * dinv) * ogv[2*p+1] * (1.0f / (1.0f + expf(-gtv[2*p+1])));
            packed[p] = packh(o0, o1);
        }
        *(uint4*)&hh[grow * 1024 + (size_t)h * 64 + e0] =
            make_uint4(packed[0], packed[1], packed[2], packed[3]);
    }
}

// ---------------------------------------------------------------------------
// Launch
// ---------------------------------------------------------------------------
extern "C" void kernel_launch(void* const* d_in, const int* in_sizes, int n_in,
                              void* d_out, int out_size)
{
    const float* x     = (const float*)d_in[0];
    const float* w_in  = (const float*)d_in[1];
    const float* w_q   = (const float*)d_in[2];
    const float* w_k   = (const float*)d_in[3];
    const float* w_v   = (const float*)d_in[4];
    const float* w_i   = (const float*)d_in[5];
    const float* b_i   = (const float*)d_in[6];
    const float* w_f   = (const float*)d_in[7];
    const float* b_f   = (const float*)d_in[8];
    const float* w_o   = (const float*)d_in[9];
    const float* b_o   = (const float*)d_in[10];
    const float* w_qn  = (const float*)d_in[11];
    const float* w_kn  = (const float*)d_in[12];
    const float* w_out = (const float*)d_in[13];
    float* out = (float*)d_out;

    float *pj, *dC, *dN, *G, *Cst, *Nst, *numI, *qdb, *denI;
    __half *xh, *hh, *wiT, *w6h, *w6l, *wff, *wof;
    cudaGetSymbolAddress((void**)&pj,   g_pj);
    cudaGetSymbolAddress((void**)&dC,   g_dC);
    cudaGetSymbolAddress((void**)&dN,   g_dN);
    cudaGetSymbolAddress((void**)&G,    g_G);
    cudaGetSymbolAddress((void**)&Cst,  g_Cst);
    cudaGetSymbolAddress((void**)&Nst,  g_Nst);
    cudaGetSymbolAddress((void**)&numI, g_numI);
    cudaGetSymbolAddress((void**)&qdb,  g_qd);
    cudaGetSymbolAddress((void**)&denI, g_denI);
    cudaGetSymbolAddress((void**)&xh,   g_xh);
    cudaGetSymbolAddress((void**)&hh,   g_hh);
    cudaGetSymbolAddress((void**)&wiT,  g_wiT);
    cudaGetSymbolAddress((void**)&w6h,  g_w6h);
    cudaGetSymbolAddress((void**)&w6l,  g_w6l);
    cudaGetSymbolAddress((void**)&wff,  g_wff);
    cudaGetSymbolAddress((void**)&wof,  g_wof);

    cudaFuncSetAttribute((const void*)gemm_f16<0,2,48,8,0>,  cudaFuncAttributeMaxDynamicSharedMemorySize, GEMM_SMEM);
    cudaFuncSetAttribute((const void*)gemm_f16<1,1,64,56,1>, cudaFuncAttributeMaxDynamicSharedMemorySize, GEMM_SMEM);
    cudaFuncSetAttribute((const void*)gemm_f16<2,1,64,8,2>,  cudaFuncAttributeMaxDynamicSharedMemorySize, GEMM_SMEM);

    // ---- pass 0: conversions (fused) + counter reset ----
    transpose_wi<<<dim3(32, 32), 256>>>(w_in, wiT);
    cvt_all<<<1024, 256>>>((const float4*)x,
                           (const float4*)(w_in + (size_t)1024 * 1024),
                           (const float4*)w_q, (const float4*)w_k, (const float4*)w_v,
                           (const float4*)w_i, (const float4*)w_f, (const float4*)w_o,
                           (const float4*)w_out,
                           (uint2*)xh, (uint2*)(wff + (size_t)6144 * 1024),
                           (uint2*)w6h, (uint2*)w6l, (uint2*)wof);

    dim3 blk(128);

    // ---- Wfused[0:6144] = Wproj @ Wi_inner (work-stealing persistent) ----
    gemm_f16<0,2,48,8,0><<<PGRID, blk, GEMM_SMEM>>>(
        w6h, w6l, 1024, wiT, nullptr, nullptr, nullptr, nullptr, nullptr,
        nullptr, 1024, wff);

    // ---- merged projections + gate from x: pj[8192,7168] ----
    gemm_f16<1,1,64,56,1><<<PGRID, blk, GEMM_SMEM>>>(
        xh, nullptr, 1024, wff, w_qn, w_kn, b_i, b_f, b_o,
        pj, NPJ, nullptr);

    // ---- chunk-parallel scan ----
    chunk_fwdA  <<<NCID, 128>>>(pj, dC, dN, G, numI, qdb, denI);
    chunk_carryP<<<dim3(BB * NH, 9), 128>>>(dC, dN, G, Cst, Nst);
    chunk_inter <<<NCID, 128>>>(pj, Cst, Nst, numI, qdb, denI, hh);

    // ---- output projection ----
    gemm_f16<2,1,64,8,2><<<PGRID, blk, GEMM_SMEM>>>(
        hh, nullptr, 1024, wof, nullptr, nullptr, nullptr, nullptr, nullptr,
        out, 1024, nullptr);
}